// round 5
// baseline (speedup 1.0000x reference)
#include <cuda_runtime.h>
#include <math.h>

typedef unsigned int u32;

// ---- problem constants ----
#define BB 8
#define TT 256
#define EE 512
#define FF 2048
#define DD 256
#define NN 2048
#define LL 2
#define VV 32000
#define HMM 4
#define HDD 64
#define HAA 8
#define DHH 64
#define IFF 1028
#define TOPKK 8
#define MAXSEL 64
#define KCAT 768

// ---- scratch (device globals; no allocations allowed) ----
__device__ float g_x[BB*TT*EE];
__device__ float g_h[BB*TT*EE];
__device__ float g_q[BB*TT*EE];
__device__ float g_k[BB*TT*EE];
__device__ float g_v[BB*TT*EE];
__device__ float g_o[BB*TT*EE];
__device__ float g_s[BB*HAA*TT*TT];
__device__ float g_u[BB*TT*FF];
__device__ float g_iface[BB*TT*IFF];
__device__ float g_mem[BB*NN*HMM*HDD];
__device__ float g_cat[BB*TT*KCAT];     // [h(512) | rv_carry(256)] per row
__device__ float g_rvbuf[2][BB*DD];     // double-buffered scan carry
__device__ u32   g_bar[BB];             // per-batch monotonic barrier

__device__ __forceinline__ float gelu_f(float x){
    float x3 = x*x*x;
    return 0.5f*x*(1.0f+tanhf(0.7978845608028654f*(x+0.044715f*x3)));
}
__device__ __forceinline__ float sigmoid_f(float x){ return 1.0f/(1.0f+expf(-x)); }
__device__ __forceinline__ float softplus_clip(float x){
    float sp = fmaxf(x,0.0f) + log1pf(expf(-fabsf(x)));
    return fminf(fmaxf(sp,1.0f),20.0f);
}

// ---- tf32 helpers ----
__device__ __forceinline__ void f32_split(float x, u32 &hi, u32 &lo){
    asm("cvt.rna.tf32.f32 %0, %1;" : "=r"(hi) : "f"(x));
    float r = x - __uint_as_float(hi);
    asm("cvt.rna.tf32.f32 %0, %1;" : "=r"(lo) : "f"(r));
}
__device__ __forceinline__ void mma_tf32(float* c, const u32* a, const u32* b){
    asm volatile("mma.sync.aligned.m16n8k8.row.col.f32.tf32.tf32.f32 "
        "{%0,%1,%2,%3}, {%4,%5,%6,%7}, {%8,%9}, {%0,%1,%2,%3};\n"
        : "+f"(c[0]), "+f"(c[1]), "+f"(c[2]), "+f"(c[3])
        : "r"(a[0]), "r"(a[1]), "r"(a[2]), "r"(a[3]), "r"(b[0]), "r"(b[1]));
}

// ---- embedding ----
__global__ void embed_kernel(const int* __restrict__ ids,
                             const float* __restrict__ emb,
                             const float* __restrict__ pos){
    int bt = blockIdx.x;
    int t = bt & (TT-1);
    int id = ids[bt];
    for (int e = threadIdx.x; e < EE; e += 256)
        g_x[(size_t)bt*EE + e] = emb[(size_t)id*EE + e] + pos[(size_t)t*EE + e];
}

// ---- layernorm (one block per row, E=512), output row stride parameterized ----
__global__ void ln_kernel(const float* __restrict__ x, const float* __restrict__ g,
                          const float* __restrict__ bb, float* __restrict__ out, int ostride){
    int row = blockIdx.x, tid = threadIdx.x;
    __shared__ float red[256];
    const float* xr = x + (size_t)row*EE;
    float v0 = xr[tid], v1 = xr[tid+256];
    red[tid] = v0+v1; __syncthreads();
    for (int s=128;s>0;s>>=1){ if (tid<s) red[tid]+=red[tid+s]; __syncthreads(); }
    float m = red[0] * (1.0f/EE);
    __syncthreads();
    float d0=v0-m, d1=v1-m;
    red[tid] = d0*d0 + d1*d1; __syncthreads();
    for (int s=128;s>0;s>>=1){ if (tid<s) red[tid]+=red[tid+s]; __syncthreads(); }
    float rs = rsqrtf(red[0]*(1.0f/EE) + 1e-5f);
    out[(size_t)row*ostride + tid]       = d0*rs*g[tid]     + bb[tid];
    out[(size_t)row*ostride + tid + 256] = d1*rs*g[tid+256] + bb[tid+256];
}

// ---- 3xTF32 tensor-core GEMM with load-time operand splitting ----
// C[M,N] (+)= A[M,K](lda) @ B[K,N] (+bias)(gelu). B rows >= Ksplit come from B2.
// Splits are done ONCE per element by the loader threads into hi/lo u32 smem
// planes; the compute loop is pure LDS + MMA.
template<bool ACC, bool GELU, bool BIAS, bool NGUARD>
__global__ __launch_bounds__(256,1)
void tgemm_kernel(const float* __restrict__ A, const float* __restrict__ B1,
                  const float* __restrict__ B2, int Ksplit,
                  const float* __restrict__ bias, float* __restrict__ C,
                  int N, int K, int lda)
{
    __shared__ u32 AsH[2][8][132];
    __shared__ u32 AsL[2][8][132];
    __shared__ u32 BsH[2][8][132];
    __shared__ u32 BsL[2][8][132];
    int tid = threadIdx.x;
    int bm = blockIdx.y*128, bn = blockIdx.x*128;
    int warp = tid>>5, lane = tid&31;
    int wm = (warp>>2)*64, wn = (warp&3)*32;
    int gid = lane>>2, tig = lane&3;

    float c[4][4][4];
    #pragma unroll
    for (int mt=0;mt<4;mt++)
        #pragma unroll
        for (int nt=0;nt<4;nt++)
            #pragma unroll
            for (int i=0;i<4;i++) c[mt][nt][i]=0.f;

    int am = tid & 127;        // A row within tile
    int ak = (tid>>7)*4;       // A k offset (0 or 4)
    int bn4 = lane*4;          // B col within tile
    int bk  = warp;            // B k row 0..7
    const float* Ap = A + (size_t)(bm+am)*lda + ak;

    int nit = K/8;

    auto loadB = [&](int it)->float4 {
        int krow = it*8 + bk;
        const float* bp = (krow < Ksplit) ? (B1 + (size_t)krow*N)
                                          : (B2 + (size_t)(krow-Ksplit)*N);
        int col = bn + bn4;
        float4 bv;
        if (!NGUARD || (col+3) < N){
            bv = *reinterpret_cast<const float4*>(bp + col);
        } else {
            bv.x = (col+0<N)? bp[col+0] : 0.f;
            bv.y = (col+1<N)? bp[col+1] : 0.f;
            bv.z = (col+2<N)? bp[col+2] : 0.f;
            bv.w = (col+3<N)? bp[col+3] : 0.f;
        }
        return bv;
    };
    auto stage = [&](int buf, float4 av, float4 bv){
        u32 h0,l0,h1,l1,h2,l2,h3,l3;
        f32_split(av.x,h0,l0); f32_split(av.y,h1,l1);
        f32_split(av.z,h2,l2); f32_split(av.w,h3,l3);
        AsH[buf][ak+0][am]=h0; AsL[buf][ak+0][am]=l0;
        AsH[buf][ak+1][am]=h1; AsL[buf][ak+1][am]=l1;
        AsH[buf][ak+2][am]=h2; AsL[buf][ak+2][am]=l2;
        AsH[buf][ak+3][am]=h3; AsL[buf][ak+3][am]=l3;
        f32_split(bv.x,h0,l0); f32_split(bv.y,h1,l1);
        f32_split(bv.z,h2,l2); f32_split(bv.w,h3,l3);
        BsH[buf][bk][bn4+0]=h0; BsL[buf][bk][bn4+0]=l0;
        BsH[buf][bk][bn4+1]=h1; BsL[buf][bk][bn4+1]=l1;
        BsH[buf][bk][bn4+2]=h2; BsL[buf][bk][bn4+2]=l2;
        BsH[buf][bk][bn4+3]=h3; BsL[buf][bk][bn4+3]=l3;
    };

    stage(0, *reinterpret_cast<const float4*>(Ap), loadB(0));
    __syncthreads();

    for (int it=0; it<nit; ++it){
        int cur = it & 1;
        float4 av2, bv2;
        bool more = (it+1) < nit;
        if (more){
            av2 = *reinterpret_cast<const float4*>(Ap + (size_t)(it+1)*8);
            bv2 = loadB(it+1);
        }
        u32 ahi[4][4], alo[4][4];
        #pragma unroll
        for (int mt=0;mt<4;mt++){
            int m0 = wm + mt*16 + gid;
            ahi[mt][0]=AsH[cur][tig  ][m0  ]; alo[mt][0]=AsL[cur][tig  ][m0  ];
            ahi[mt][1]=AsH[cur][tig  ][m0+8]; alo[mt][1]=AsL[cur][tig  ][m0+8];
            ahi[mt][2]=AsH[cur][tig+4][m0  ]; alo[mt][2]=AsL[cur][tig+4][m0  ];
            ahi[mt][3]=AsH[cur][tig+4][m0+8]; alo[mt][3]=AsL[cur][tig+4][m0+8];
        }
        u32 bhi[4][2], blo[4][2];
        #pragma unroll
        for (int nt=0;nt<4;nt++){
            int n0 = wn + nt*8 + gid;
            bhi[nt][0]=BsH[cur][tig  ][n0]; blo[nt][0]=BsL[cur][tig  ][n0];
            bhi[nt][1]=BsH[cur][tig+4][n0]; blo[nt][1]=BsL[cur][tig+4][n0];
        }
        #pragma unroll
        for (int mt=0;mt<4;mt++){
            #pragma unroll
            for (int nt=0;nt<4;nt++){
                mma_tf32(c[mt][nt], ahi[mt], bhi[nt]);
                mma_tf32(c[mt][nt], ahi[mt], blo[nt]);
                mma_tf32(c[mt][nt], alo[mt], bhi[nt]);
            }
        }
        if (more){
            stage(cur^1, av2, bv2);
            __syncthreads();
        }
    }

    #pragma unroll
    for (int mt=0;mt<4;mt++){
        int ra = bm + wm + mt*16 + gid;
        int rb = ra + 8;
        #pragma unroll
        for (int nt=0;nt<4;nt++){
            int col = bn + wn + nt*8 + tig*2;
            #pragma unroll
            for (int q=0;q<4;q++){
                int r = (q<2)? ra : rb;
                int cc = col + (q&1);
                if (NGUARD && cc >= N) continue;
                float v = c[mt][nt][q];
                if (BIAS) v += bias[cc];
                if (GELU) v = gelu_f(v);
                size_t idx = (size_t)r*N + cc;
                if (ACC) v += C[idx];
                C[idx] = v;
            }
        }
    }
}

// ---- attention: scores S = QK^T/8 with causal mask ----
__global__ void attn_s_kernel(){
    int bh = blockIdx.y;
    int b = bh >> 3, h = bh & 7;
    int qt = blockIdx.x >> 3, kt = blockIdx.x & 7;
    __shared__ float Qs[32][65];
    __shared__ float Ks[32][65];
    int tid = threadIdx.x;
    {
        int r = tid >> 3, cc = (tid & 7)*8;
        const float* qsrc = g_q + ((size_t)(b*TT + qt*32 + r))*EE + h*DHH + cc;
        const float* ksrc = g_k + ((size_t)(b*TT + kt*32 + r))*EE + h*DHH + cc;
        float4 q0 = *(const float4*)qsrc, q1 = *(const float4*)(qsrc+4);
        float4 k0 = *(const float4*)ksrc, k1 = *(const float4*)(ksrc+4);
        Qs[r][cc+0]=q0.x; Qs[r][cc+1]=q0.y; Qs[r][cc+2]=q0.z; Qs[r][cc+3]=q0.w;
        Qs[r][cc+4]=q1.x; Qs[r][cc+5]=q1.y; Qs[r][cc+6]=q1.z; Qs[r][cc+7]=q1.w;
        Ks[r][cc+0]=k0.x; Ks[r][cc+1]=k0.y; Ks[r][cc+2]=k0.z; Ks[r][cc+3]=k0.w;
        Ks[r][cc+4]=k1.x; Ks[r][cc+5]=k1.y; Ks[r][cc+6]=k1.z; Ks[r][cc+7]=k1.w;
    }
    __syncthreads();
    int r = tid & 31, gq = tid >> 5;
    float a0=0,a1=0,a2=0,a3=0;
    #pragma unroll
    for (int kk=0;kk<64;kk++){
        float qv = Qs[r][kk];
        a0 += qv*Ks[gq*4+0][kk];
        a1 += qv*Ks[gq*4+1][kk];
        a2 += qv*Ks[gq*4+2][kk];
        a3 += qv*Ks[gq*4+3][kk];
    }
    int qrow = qt*32 + r;
    int kc = kt*32 + gq*4;
    float* srow = g_s + ((size_t)bh*TT + qrow)*TT + kc;
    srow[0] = (kc+0<=qrow)? a0*0.125f : -1e30f;
    srow[1] = (kc+1<=qrow)? a1*0.125f : -1e30f;
    srow[2] = (kc+2<=qrow)? a2*0.125f : -1e30f;
    srow[3] = (kc+3<=qrow)? a3*0.125f : -1e30f;
}

// ---- attention: row softmax in-place on g_s ----
__global__ void softmax_kernel(){
    int row = blockIdx.x, tid = threadIdx.x;
    __shared__ float red[256];
    float* sp = g_s + (size_t)row*TT;
    float v = sp[tid];
    red[tid]=v; __syncthreads();
    for (int s=128;s>0;s>>=1){ if (tid<s) red[tid]=fmaxf(red[tid],red[tid+s]); __syncthreads(); }
    float m = red[0]; __syncthreads();
    float e = expf(v-m);
    red[tid]=e; __syncthreads();
    for (int s=128;s>0;s>>=1){ if (tid<s) red[tid]+=red[tid+s]; __syncthreads(); }
    sp[tid] = e / red[0];
}

// ---- attention: O = A @ V ----
__global__ void attn_o_kernel(){
    int bh = blockIdx.y;
    int b = bh >> 3, h = bh & 7;
    int qt = blockIdx.x;
    __shared__ float As[32][65];
    __shared__ float Vs[64][64];
    int tid = threadIdx.x;
    int d = tid & 63, qg = tid >> 6;
    float acc[8];
    #pragma unroll
    for (int i=0;i<8;i++) acc[i]=0.f;
    for (int k0=0;k0<TT;k0+=64){
        {
            int r = tid >> 3, cc = (tid & 7)*8;
            const float* src = g_s + ((size_t)bh*TT + qt*32 + r)*TT + k0 + cc;
            float4 a0=*(const float4*)src, a1=*(const float4*)(src+4);
            As[r][cc+0]=a0.x; As[r][cc+1]=a0.y; As[r][cc+2]=a0.z; As[r][cc+3]=a0.w;
            As[r][cc+4]=a1.x; As[r][cc+5]=a1.y; As[r][cc+6]=a1.z; As[r][cc+7]=a1.w;
        }
        #pragma unroll
        for (int i=0;i<4;i++){
            int fl = (tid + 256*i)*4;
            int r = fl >> 6, cc = fl & 63;
            float4 vv = *(const float4*)(g_v + ((size_t)(b*TT + k0 + r))*EE + h*DHH + cc);
            *(float4*)&Vs[r][cc] = vv;
        }
        __syncthreads();
        #pragma unroll
        for (int kk=0;kk<64;kk++){
            float vv = Vs[kk][d];
            #pragma unroll
            for (int i=0;i<8;i++) acc[i] += As[qg*8+i][kk]*vv;
        }
        __syncthreads();
    }
    #pragma unroll
    for (int i=0;i<8;i++){
        int qr = qt*32 + qg*8 + i;
        g_o[((size_t)(b*TT + qr))*EE + h*DHH + d] = acc[i];
    }
}

// ---- memory init / scan-state init (rvbuf[0]=0, barriers=0) ----
__global__ void meminit_kernel(const float* __restrict__ mi){
    int idx = blockIdx.x*256 + threadIdx.x;
    g_mem[idx] = mi[idx & (NN*DD - 1)];
}
__global__ void scaninit_kernel(){
    int i = blockIdx.x*256 + threadIdx.x;
    g_rvbuf[0][i] = 0.f;
    if (i < BB) g_bar[i] = 0u;
}

// ---- persistent fused scan: one launch, 32 resident blocks (b,h), 256 steps ----
__global__ __launch_bounds__(256,1)
void scan_persist_kernel(const float* __restrict__ Wr,
                         const float* __restrict__ pbr,
                         const float* __restrict__ pbw)
{
    int bh = blockIdx.x;
    int b = bh >> 2, h = bh & 3;
    int tid = threadIdx.x;   // 256

    __shared__ float rv_s[DD];
    __shared__ float ifc_s[256];   // rk[0:64) wk[64:128) wv[128:192) er[192:256)
    __shared__ float knr[HDD], knw[HDD];
    __shared__ float simr[NN], simw[NN], swork[NN];
    __shared__ float gr_sh;
    __shared__ float redv[8]; __shared__ int redi[8];
    __shared__ float kv8[TOPKK];
    __shared__ int s_cnt;
    __shared__ int sel_idx[MAXSEL];
    __shared__ float sel_w[MAXSEL];
    __shared__ float s_inv;

    float beta_r = softplus_clip(*pbr);
    float beta_w = softplus_clip(*pbw);

    for (int t=0; t<TT; ++t){
        // carry rv for this step (L1-bypassing load: written by peer SMs)
        rv_s[tid] = __ldcg(&g_rvbuf[t&1][b*DD + tid]);
        __syncthreads();
        if (h == 0)
            g_cat[(size_t)(b*TT + t)*KCAT + 512 + tid] = rv_s[tid];

        // iface columns for this (b,h): i = iface_gemm(bias folded) + rv @ W_if_r
        {
            int grp = tid >> 6, l = tid & 63;
            int col = grp*DD + h*HDD + l;
            float acc = g_iface[(size_t)(b*TT + t)*IFF + col];
            #pragma unroll 4
            for (int d=0; d<DD; ++d) acc += rv_s[d]*Wr[(size_t)d*IFF + col];
            ifc_s[tid] = acc;
        }
        if (tid < 32){
            int col = 4*DD + h;
            float acc = 0.f;
            for (int d=tid; d<DD; d+=32) acc += rv_s[d]*Wr[(size_t)d*IFF + col];
            #pragma unroll
            for (int o=16;o>0;o>>=1) acc += __shfl_xor_sync(0xffffffffu, acc, o);
            if (tid==0) gr_sh = acc + g_iface[(size_t)(b*TT + t)*IFF + col];
        }
        __syncthreads();

        // normalize keys
        if (tid < 64){
            int w = tid >> 5, l = tid & 31;
            float v0 = ifc_s[w*64 + l], v1 = ifc_s[w*64 + l + 32];
            float ss = v0*v0 + v1*v1;
            #pragma unroll
            for (int o=16;o>0;o>>=1) ss += __shfl_xor_sync(0xffffffffu, ss, o);
            float rn = rsqrtf(ss + 1e-8f);
            float* dst = w ? knw : knr;
            dst[l] = v0*rn; dst[l+32] = v1*rn;
        }
        __syncthreads();

        // sims: single pass over this block's private memory slice
        {
            int warp = tid >> 5, lane = tid & 31;
            int oct = lane >> 3, r = lane & 7;
            float4 kr0 = *(const float4*)&knr[r*8], kr1 = *(const float4*)&knr[r*8+4];
            float4 kw0 = *(const float4*)&knw[r*8], kw1 = *(const float4*)&knw[r*8+4];
            for (int it=0; it<NN/32; ++it){
                int n = it*32 + warp*4 + oct;
                const float* mrow = g_mem + (((size_t)b*NN + n)*HMM + h)*HDD + r*8;
                float4 m0 = *(const float4*)mrow, m1 = *(const float4*)(mrow+4);
                float ss = m0.x*m0.x+m0.y*m0.y+m0.z*m0.z+m0.w*m0.w
                         + m1.x*m1.x+m1.y*m1.y+m1.z*m1.z+m1.w*m1.w;
                float dr = m0.x*kr0.x+m0.y*kr0.y+m0.z*kr0.z+m0.w*kr0.w
                         + m1.x*kr1.x+m1.y*kr1.y+m1.z*kr1.z+m1.w*kr1.w;
                float dw = m0.x*kw0.x+m0.y*kw0.y+m0.z*kw0.z+m0.w*kw0.w
                         + m1.x*kw1.x+m1.y*kw1.y+m1.z*kw1.z+m1.w*kw1.w;
                #pragma unroll
                for (int o=4;o>0;o>>=1){
                    ss += __shfl_xor_sync(0xffffffffu, ss, o);
                    dr += __shfl_xor_sync(0xffffffffu, dr, o);
                    dw += __shfl_xor_sync(0xffffffffu, dw, o);
                }
                if (r == 0){
                    float rn = rsqrtf(ss + 1e-8f);
                    simr[n] = dr*rn;
                    simw[n] = dw*rn;
                }
            }
        }
        __syncthreads();

        for (int phase=0; phase<2; ++phase){
            float beta = phase ? beta_w : beta_r;
            float* sim = phase ? simw : simr;
            for (int i=tid;i<NN;i+=256) swork[i]=sim[i];
            if (tid==0) s_cnt = 0;
            __syncthreads();
            // top-8 via iterative warp-reduced argmax
            for (int it=0; it<TOPKK; ++it){
                float bv = -3.4e38f; int bi = 0;
                #pragma unroll
                for (int j=0;j<NN/256;j++){
                    int i = tid + j*256;
                    float v = swork[i];
                    if (v > bv){ bv=v; bi=i; }
                }
                #pragma unroll
                for (int o=16;o>0;o>>=1){
                    float ov = __shfl_xor_sync(0xffffffffu, bv, o);
                    int   oi = __shfl_xor_sync(0xffffffffu, bi, o);
                    if (ov > bv){ bv=ov; bi=oi; }
                }
                if ((tid&31)==0){ redv[tid>>5]=bv; redi[tid>>5]=bi; }
                __syncthreads();
                if (tid==0){
                    float m = redv[0]; int mi = redi[0];
                    #pragma unroll
                    for (int w=1;w<8;w++) if (redv[w]>m){ m=redv[w]; mi=redi[w]; }
                    kv8[it]=m; swork[mi] = -3.4e38f;
                }
                __syncthreads();
            }
            float kth = kv8[TOPKK-1], smax = kv8[0];
            for (int i=tid;i<NN;i+=256){
                float v = sim[i];
                if (v >= kth){
                    int p = atomicAdd(&s_cnt, 1);
                    if (p < MAXSEL){ sel_idx[p]=i; sel_w[p]=expf(beta*(v-smax)); }
                }
            }
            __syncthreads();
            int cnt = min(s_cnt, MAXSEL);
            if (tid==0){
                float ds=0.f;
                for (int j=0;j<cnt;j++) ds += sel_w[j];
                s_inv = 1.0f/ds;
            }
            __syncthreads();
            float invd = s_inv;
            if (phase==0){
                if (tid < HDD){
                    float acc=0.f;
                    for (int j=0;j<cnt;j++)
                        acc += sel_w[j]*invd * g_mem[(((size_t)b*NN + sel_idx[j])*HMM + h)*HDD + tid];
                    __stcg(&g_rvbuf[(t+1)&1][b*DD + h*HDD + tid], acc);
                }
                __syncthreads();
                // publish rv for peers, then arrive at per-batch barrier
                if (tid==0){
                    __threadfence();
                    atomicAdd(&g_bar[b], 1u);
                }
            } else {
                float gg = sigmoid_f(gr_sh);
                int d = tid & 63;
                float ee = sigmoid_f(ifc_s[192 + d]);
                float gv = gg * ifc_s[128 + d];
                for (int j = tid>>6; j<cnt; j+=4){
                    float w = sel_w[j]*invd;
                    size_t mi = (((size_t)b*NN + sel_idx[j])*HMM + h)*HDD + d;
                    g_mem[mi] = g_mem[mi]*(1.0f - w*ee) + w*gv;
                }
            }
            __syncthreads();
        }

        // wait for all 4 head-blocks of this batch to finish step t
        if (tid==0){
            while (atomicAdd(&g_bar[b], 0u) < 4u*(unsigned)(t+1)) { }
        }
        __syncthreads();
    }
}

extern "C" void kernel_launch(void* const* d_in, const int* in_sizes, int n_in,
                              void* d_out, int out_size)
{
    const int*   ids      = (const int*)  d_in[0];
    const float* emb      = (const float*)d_in[1];
    const float* pos      = (const float*)d_in[2];
    const float* ln1_g    = (const float*)d_in[3];
    const float* ln1_b    = (const float*)d_in[4];
    const float* ln2_g    = (const float*)d_in[5];
    const float* ln2_b    = (const float*)d_in[6];
    const float* Wq       = (const float*)d_in[7];
    const float* Wk       = (const float*)d_in[8];
    const float* Wv       = (const float*)d_in[9];
    const float* Wo       = (const float*)d_in[10];
    const float* W1       = (const float*)d_in[11];
    const float* b1       = (const float*)d_in[12];
    const float* W2       = (const float*)d_in[13];
    const float* b2       = (const float*)d_in[14];
    const float* lnf_g    = (const float*)d_in[15];
    const float* lnf_b    = (const float*)d_in[16];
    const float* W_if_h   = (const float*)d_in[17];
    const float* W_if_r   = (const float*)d_in[18];
    const float* b_if     = (const float*)d_in[19];
    const float* W_lg_h   = (const float*)d_in[20];
    const float* W_lg_r   = (const float*)d_in[21];
    const float* b_lg     = (const float*)d_in[22];
    const float* beta_read  = (const float*)d_in[23];
    const float* beta_write = (const float*)d_in[24];
    const float* mem_init = (const float*)d_in[25];
    float* out = (float*)d_out;

    float *px,*phh,*pq,*pk,*pv,*po,*pu,*pif,*pcat;
    cudaGetSymbolAddress((void**)&px,  g_x);
    cudaGetSymbolAddress((void**)&phh, g_h);
    cudaGetSymbolAddress((void**)&pq,  g_q);
    cudaGetSymbolAddress((void**)&pk,  g_k);
    cudaGetSymbolAddress((void**)&pv,  g_v);
    cudaGetSymbolAddress((void**)&po,  g_o);
    cudaGetSymbolAddress((void**)&pu,  g_u);
    cudaGetSymbolAddress((void**)&pif, g_iface);
    cudaGetSymbolAddress((void**)&pcat,g_cat);

    const int M = BB*TT;  // 2048

    embed_kernel<<<M,256>>>(ids, emb, pos);

    for (int l=0; l<LL; ++l){
        ln_kernel<<<M,256>>>(px, ln1_g + l*EE, ln1_b + l*EE, phh, EE);
        tgemm_kernel<false,false,false,false><<<dim3(4,16),256>>>(phh, Wq + (size_t)l*EE*EE, Wq, EE, nullptr, pq, EE, EE, EE);
        tgemm_kernel<false,false,false,false><<<dim3(4,16),256>>>(phh, Wk + (size_t)l*EE*EE, Wk, EE, nullptr, pk, EE, EE, EE);
        tgemm_kernel<false,false,false,false><<<dim3(4,16),256>>>(phh, Wv + (size_t)l*EE*EE, Wv, EE, nullptr, pv, EE, EE, EE);
        attn_s_kernel<<<dim3(64, BB*HAA),256>>>();
        softmax_kernel<<<BB*HAA*TT,256>>>();
        attn_o_kernel<<<dim3(8, BB*HAA),256>>>();
        tgemm_kernel<true,false,false,false><<<dim3(4,16),256>>>(po, Wo + (size_t)l*EE*EE, Wo, EE, nullptr, px, EE, EE, EE);
        ln_kernel<<<M,256>>>(px, ln2_g + l*EE, ln2_b + l*EE, phh, EE);
        tgemm_kernel<false,true,true,false><<<dim3(16,16),256>>>(phh, W1 + (size_t)l*EE*FF, W1, EE, b1 + l*FF, pu, FF, EE, EE);
        tgemm_kernel<true,false,true,false><<<dim3(4,16),256>>>(pu, W2 + (size_t)l*FF*EE, W2, FF, b2 + l*EE, px, EE, FF, FF);
    }

    // final LN -> g_cat cols [0,512) with stride 768
    ln_kernel<<<M,256>>>(px, lnf_g, lnf_b, pcat, KCAT);

    // iface = h @ W_if_h + b_if   (bias folded here; scan adds rv@W_if_r)
    tgemm_kernel<false,false,true,true><<<dim3(9,16),256>>>(pcat, W_if_h, W_if_h, EE, b_if, pif, IFF, EE, KCAT);

    meminit_kernel<<<16384,256>>>(mem_init);
    scaninit_kernel<<<8,256>>>();

    // single persistent launch: 32 blocks = (b,h), 256 steps internally
    scan_persist_kernel<<<BB*HMM,256>>>(W_if_r, beta_read, beta_write);

    // out = [h | rv_carry] @ [W_lg_h ; W_lg_r] + b_lg   (single fused vocab GEMM)
    tgemm_kernel<false,false,true,false><<<dim3(250,16),256>>>(pcat, W_lg_h, W_lg_r, EE, b_lg, out, VV, KCAT, KCAT);
}

// round 6
// speedup vs baseline: 1.4045x; 1.4045x over previous
#include <cuda_runtime.h>
#include <math.h>

typedef unsigned int u32;

#define BB 8
#define TT 256
#define EE 512
#define FF 2048
#define DD 256
#define NN 2048
#define LL 2
#define VV 32000
#define HMM 4
#define HDD 64
#define HAA 8
#define DHH 64
#define IFF 1028
#define TOPKK 8
#define MAXSEL 64
#define KCAT 768

// weight-plane arena offsets (u32 units)
#define OFF_QKVO(l,w) (((l)*4+(w))*131072)
#define OFF_W1(l) (1048576 + (l)*524288)
#define OFF_W2(l) (2097152 + (l)*524288)
#define OFF_WIFH 3145728
#define OFF_WLG  3408896
#define ARENA    15696896

// ---- scratch ----
__device__ float g_x[BB*TT*EE];
__device__ float g_h[BB*TT*EE];
__device__ float g_q[BB*TT*EE];
__device__ float g_k[BB*TT*EE];
__device__ float g_v[BB*TT*EE];
__device__ float g_o[BB*TT*EE];
__device__ float g_s[BB*HAA*TT*TT];
__device__ float g_u[BB*TT*FF];
__device__ float g_iface[BB*TT*IFF];
__device__ float g_mem[BB*NN*HMM*HDD];
__device__ float g_cat[BB*TT*KCAT];
__device__ float g_rvbuf[2][BB*DD];
__device__ u32   g_bar[BB];
__device__ u32   g_wh[ARENA];
__device__ u32   g_wl[ARENA];
__device__ u32   g_ah[2048*1024];
__device__ u32   g_al[2048*1024];

__device__ __forceinline__ float gelu_f(float x){
    float x3 = x*x*x;
    return 0.5f*x*(1.0f+tanhf(0.7978845608028654f*(x+0.044715f*x3)));
}
__device__ __forceinline__ float sigmoid_f(float x){ return 1.0f/(1.0f+expf(-x)); }
__device__ __forceinline__ float softplus_clip(float x){
    float sp = fmaxf(x,0.0f) + log1pf(expf(-fabsf(x)));
    return fminf(fmaxf(sp,1.0f),20.0f);
}

// pack (even,odd) k-pair into hi/lo bf16x2 (low half = even k)
__device__ __forceinline__ void packpair(float e, float o, u32 &hi, u32 &lo){
    u32 h; asm("cvt.rn.bf16x2.f32 %0, %1, %2;" : "=r"(h) : "f"(o), "f"(e));
    float he = __uint_as_float(h<<16);
    float ho = __uint_as_float(h & 0xffff0000u);
    asm("cvt.rn.bf16x2.f32 %0, %1, %2;" : "=r"(lo) : "f"(o-ho), "f"(e-he));
    hi = h;
}

__device__ __forceinline__ void mma_bf16(float* c, const u32* a, const u32* b){
    asm volatile("mma.sync.aligned.m16n8k16.row.col.f32.bf16.bf16.f32 "
        "{%0,%1,%2,%3}, {%4,%5,%6,%7}, {%8,%9}, {%0,%1,%2,%3};\n"
        : "+f"(c[0]), "+f"(c[1]), "+f"(c[2]), "+f"(c[3])
        : "r"(a[0]), "r"(a[1]), "r"(a[2]), "r"(a[3]), "r"(b[0]), "r"(b[1]));
}

// ---- weight split: f32 [K][N] -> hi/lo u32 planes [K/2][N] ----
__global__ void wsplit_kernel(const float* __restrict__ src, u32* __restrict__ dh,
                              u32* __restrict__ dl, int N){
    int k2 = blockIdx.y;
    int n = blockIdx.x*256 + threadIdx.x;
    if (n >= N) return;
    float e = src[(size_t)(2*k2)*N + n];
    float o = src[(size_t)(2*k2+1)*N + n];
    u32 hi, lo; packpair(e, o, hi, lo);
    dh[(size_t)k2*N + n] = hi;
    dl[(size_t)k2*N + n] = lo;
}

// ---- activation split: f32 [M][lds] cols 2*kp,2*kp+1 -> planes [M][lda2] at kpo ----
__global__ void asplit_kernel(const float* __restrict__ src, int lds,
                              u32* __restrict__ dh, u32* __restrict__ dl,
                              int lda2, int kpo, int nkp){
    int row = blockIdx.x;
    for (int kp = threadIdx.x; kp < nkp; kp += 256){
        float e = src[(size_t)row*lds + 2*kp];
        float o = src[(size_t)row*lds + 2*kp + 1];
        u32 hi, lo; packpair(e, o, hi, lo);
        dh[(size_t)row*lda2 + kpo + kp] = hi;
        dl[(size_t)row*lda2 + kpo + kp] = lo;
    }
}

// ---- embedding ----
__global__ void embed_kernel(const int* __restrict__ ids,
                             const float* __restrict__ emb,
                             const float* __restrict__ pos){
    int bt = blockIdx.x;
    int t = bt & (TT-1);
    int id = ids[bt];
    for (int e = threadIdx.x; e < EE; e += 256)
        g_x[(size_t)bt*EE + e] = emb[(size_t)id*EE + e] + pos[(size_t)t*EE + e];
}

// ---- layernorm ----
__global__ void ln_kernel(const float* __restrict__ x, const float* __restrict__ g,
                          const float* __restrict__ bb, float* __restrict__ out, int ostride){
    int row = blockIdx.x, tid = threadIdx.x;
    __shared__ float red[256];
    const float* xr = x + (size_t)row*EE;
    float v0 = xr[tid], v1 = xr[tid+256];
    red[tid] = v0+v1; __syncthreads();
    for (int s=128;s>0;s>>=1){ if (tid<s) red[tid]+=red[tid+s]; __syncthreads(); }
    float m = red[0] * (1.0f/EE);
    __syncthreads();
    float d0=v0-m, d1=v1-m;
    red[tid] = d0*d0 + d1*d1; __syncthreads();
    for (int s=128;s>0;s>>=1){ if (tid<s) red[tid]+=red[tid+s]; __syncthreads(); }
    float rs = rsqrtf(red[0]*(1.0f/EE) + 1e-5f);
    out[(size_t)row*ostride + tid]       = d0*rs*g[tid]     + bb[tid];
    out[(size_t)row*ostride + tid + 256] = d1*rs*g[tid+256] + bb[tid+256];
}

// ---- bf16x3 tensor GEMM: C[M,N](+)=A@B. A planes [M][lda2], B planes [K2][N]. ----
template<bool ACC, bool GELU, bool BIAS, bool NGUARD>
__global__ __launch_bounds__(256,1)
void bgemm_kernel(const u32* __restrict__ AH, const u32* __restrict__ AL, int lda2,
                  const u32* __restrict__ BH, const u32* __restrict__ BL,
                  const float* __restrict__ bias, float* __restrict__ C,
                  int N, int K2)
{
    __shared__ u32 AsH[2][8][136], AsL[2][8][136];
    __shared__ u32 BsH[2][8][136], BsL[2][8][136];
    int tid = threadIdx.x;
    int bm = blockIdx.y*128, bn = blockIdx.x*128;
    int warp = tid>>5, lane = tid&31;
    int wm = (warp>>2)*64, wn = (warp&3)*32;
    int gid = lane>>2, tig = lane&3;

    float c[4][4][4];
    #pragma unroll
    for (int mt=0;mt<4;mt++)
        #pragma unroll
        for (int nt=0;nt<4;nt++)
            #pragma unroll
            for (int i=0;i<4;i++) c[mt][nt][i]=0.f;

    int am = tid & 127, akp = (tid>>7)*4;
    int bk = tid>>5, bn4 = lane*4;
    const u32* AHp = AH + (size_t)(bm+am)*lda2 + akp;
    const u32* ALp = AL + (size_t)(bm+am)*lda2 + akp;
    int nit = K2/8;

    auto loadB = [&](const u32* Bp, int it)->uint4 {
        int kr = it*8 + bk;
        const u32* p = Bp + (size_t)kr*N + bn + bn4;
        int col = bn + bn4;
        if (!NGUARD || (col+3) < N) return *reinterpret_cast<const uint4*>(p);
        uint4 v;
        v.x = (col+0<N)?p[0]:0u; v.y = (col+1<N)?p[1]:0u;
        v.z = (col+2<N)?p[2]:0u; v.w = (col+3<N)?p[3]:0u;
        return v;
    };
    auto stage = [&](int buf, uint4 ah_, uint4 al_, uint4 bh_, uint4 bl_){
        AsH[buf][akp+0][am]=ah_.x; AsH[buf][akp+1][am]=ah_.y;
        AsH[buf][akp+2][am]=ah_.z; AsH[buf][akp+3][am]=ah_.w;
        AsL[buf][akp+0][am]=al_.x; AsL[buf][akp+1][am]=al_.y;
        AsL[buf][akp+2][am]=al_.z; AsL[buf][akp+3][am]=al_.w;
        *reinterpret_cast<uint4*>(&BsH[buf][bk][bn4]) = bh_;
        *reinterpret_cast<uint4*>(&BsL[buf][bk][bn4]) = bl_;
    };

    stage(0, *reinterpret_cast<const uint4*>(AHp), *reinterpret_cast<const uint4*>(ALp),
          loadB(BH,0), loadB(BL,0));
    __syncthreads();

    for (int it=0; it<nit; ++it){
        int cur = it & 1;
        uint4 ah2, al2, bh2, bl2;
        bool more = (it+1) < nit;
        if (more){
            ah2 = *reinterpret_cast<const uint4*>(AHp + (size_t)(it+1)*8);
            al2 = *reinterpret_cast<const uint4*>(ALp + (size_t)(it+1)*8);
            bh2 = loadB(BH, it+1);
            bl2 = loadB(BL, it+1);
        }
        u32 aH[4][4], aL[4][4];
        #pragma unroll
        for (int mt=0;mt<4;mt++){
            int m0 = wm + mt*16 + gid;
            aH[mt][0]=AsH[cur][tig  ][m0  ]; aL[mt][0]=AsL[cur][tig  ][m0  ];
            aH[mt][1]=AsH[cur][tig  ][m0+8]; aL[mt][1]=AsL[cur][tig  ][m0+8];
            aH[mt][2]=AsH[cur][tig+4][m0  ]; aL[mt][2]=AsL[cur][tig+4][m0  ];
            aH[mt][3]=AsH[cur][tig+4][m0+8]; aL[mt][3]=AsL[cur][tig+4][m0+8];
        }
        u32 bH[4][2], bL[4][2];
        #pragma unroll
        for (int nt=0;nt<4;nt++){
            int n0 = wn + nt*8 + gid;
            bH[nt][0]=BsH[cur][tig  ][n0]; bL[nt][0]=BsL[cur][tig  ][n0];
            bH[nt][1]=BsH[cur][tig+4][n0]; bL[nt][1]=BsL[cur][tig+4][n0];
        }
        #pragma unroll
        for (int mt=0;mt<4;mt++){
            #pragma unroll
            for (int nt=0;nt<4;nt++){
                mma_bf16(c[mt][nt], aH[mt], bH[nt]);
                mma_bf16(c[mt][nt], aH[mt], bL[nt]);
                mma_bf16(c[mt][nt], aL[mt], bH[nt]);
            }
        }
        if (more){
            stage(cur^1, ah2, al2, bh2, bl2);
            __syncthreads();
        }
    }

    #pragma unroll
    for (int mt=0;mt<4;mt++){
        int ra = bm + wm + mt*16 + gid;
        int rb = ra + 8;
        #pragma unroll
        for (int nt=0;nt<4;nt++){
            int col = bn + wn + nt*8 + tig*2;
            #pragma unroll
            for (int q=0;q<4;q++){
                int r = (q<2)? ra : rb;
                int cc = col + (q&1);
                if (NGUARD && cc >= N) continue;
                float v = c[mt][nt][q];
                if (BIAS) v += bias[cc];
                if (GELU) v = gelu_f(v);
                size_t idx = (size_t)r*N + cc;
                if (ACC) v += C[idx];
                C[idx] = v;
            }
        }
    }
}

// ---- attention ----
__global__ void attn_s_kernel(){
    int bh = blockIdx.y;
    int b = bh >> 3, h = bh & 7;
    int qt = blockIdx.x >> 3, kt = blockIdx.x & 7;
    __shared__ float Qs[32][65];
    __shared__ float Ks[32][65];
    int tid = threadIdx.x;
    {
        int r = tid >> 3, cc = (tid & 7)*8;
        const float* qsrc = g_q + ((size_t)(b*TT + qt*32 + r))*EE + h*DHH + cc;
        const float* ksrc = g_k + ((size_t)(b*TT + kt*32 + r))*EE + h*DHH + cc;
        float4 q0 = *(const float4*)qsrc, q1 = *(const float4*)(qsrc+4);
        float4 k0 = *(const float4*)ksrc, k1 = *(const float4*)(ksrc+4);
        Qs[r][cc+0]=q0.x; Qs[r][cc+1]=q0.y; Qs[r][cc+2]=q0.z; Qs[r][cc+3]=q0.w;
        Qs[r][cc+4]=q1.x; Qs[r][cc+5]=q1.y; Qs[r][cc+6]=q1.z; Qs[r][cc+7]=q1.w;
        Ks[r][cc+0]=k0.x; Ks[r][cc+1]=k0.y; Ks[r][cc+2]=k0.z; Ks[r][cc+3]=k0.w;
        Ks[r][cc+4]=k1.x; Ks[r][cc+5]=k1.y; Ks[r][cc+6]=k1.z; Ks[r][cc+7]=k1.w;
    }
    __syncthreads();
    int r = tid & 31, gq = tid >> 5;
    float a0=0,a1=0,a2=0,a3=0;
    #pragma unroll
    for (int kk=0;kk<64;kk++){
        float qv = Qs[r][kk];
        a0 += qv*Ks[gq*4+0][kk];
        a1 += qv*Ks[gq*4+1][kk];
        a2 += qv*Ks[gq*4+2][kk];
        a3 += qv*Ks[gq*4+3][kk];
    }
    int qrow = qt*32 + r;
    int kc = kt*32 + gq*4;
    float* srow = g_s + ((size_t)bh*TT + qrow)*TT + kc;
    srow[0] = (kc+0<=qrow)? a0*0.125f : -1e30f;
    srow[1] = (kc+1<=qrow)? a1*0.125f : -1e30f;
    srow[2] = (kc+2<=qrow)? a2*0.125f : -1e30f;
    srow[3] = (kc+3<=qrow)? a3*0.125f : -1e30f;
}

__global__ void softmax_kernel(){
    int row = blockIdx.x, tid = threadIdx.x;
    __shared__ float red[256];
    float* sp = g_s + (size_t)row*TT;
    float v = sp[tid];
    red[tid]=v; __syncthreads();
    for (int s=128;s>0;s>>=1){ if (tid<s) red[tid]=fmaxf(red[tid],red[tid+s]); __syncthreads(); }
    float m = red[0]; __syncthreads();
    float e = expf(v-m);
    red[tid]=e; __syncthreads();
    for (int s=128;s>0;s>>=1){ if (tid<s) red[tid]+=red[tid+s]; __syncthreads(); }
    sp[tid] = e / red[0];
}

__global__ void attn_o_kernel(){
    int bh = blockIdx.y;
    int b = bh >> 3, h = bh & 7;
    int qt = blockIdx.x;
    __shared__ float As[32][65];
    __shared__ float Vs[64][64];
    int tid = threadIdx.x;
    int d = tid & 63, qg = tid >> 6;
    float acc[8];
    #pragma unroll
    for (int i=0;i<8;i++) acc[i]=0.f;
    for (int k0=0;k0<TT;k0+=64){
        {
            int r = tid >> 3, cc = (tid & 7)*8;
            const float* src = g_s + ((size_t)bh*TT + qt*32 + r)*TT + k0 + cc;
            float4 a0=*(const float4*)src, a1=*(const float4*)(src+4);
            As[r][cc+0]=a0.x; As[r][cc+1]=a0.y; As[r][cc+2]=a0.z; As[r][cc+3]=a0.w;
            As[r][cc+4]=a1.x; As[r][cc+5]=a1.y; As[r][cc+6]=a1.z; As[r][cc+7]=a1.w;
        }
        #pragma unroll
        for (int i=0;i<4;i++){
            int fl = (tid + 256*i)*4;
            int r = fl >> 6, cc = fl & 63;
            float4 vv = *(const float4*)(g_v + ((size_t)(b*TT + k0 + r))*EE + h*DHH + cc);
            *(float4*)&Vs[r][cc] = vv;
        }
        __syncthreads();
        #pragma unroll
        for (int kk=0;kk<64;kk++){
            float vv = Vs[kk][d];
            #pragma unroll
            for (int i=0;i<8;i++) acc[i] += As[qg*8+i][kk]*vv;
        }
        __syncthreads();
    }
    #pragma unroll
    for (int i=0;i<8;i++){
        int qr = qt*32 + qg*8 + i;
        g_o[((size_t)(b*TT + qr))*EE + h*DHH + d] = acc[i];
    }
}

// ---- init ----
__global__ void meminit_kernel(const float* __restrict__ mi){
    int idx = blockIdx.x*256 + threadIdx.x;
    g_mem[idx] = mi[idx & (NN*DD - 1)];
}
__global__ void scaninit_kernel(){
    int i = blockIdx.x*256 + threadIdx.x;
    g_rvbuf[0][i] = 0.f;
    if (i < BB) g_bar[i] = 0u;
}

// ---- persistent fused scan ----
__global__ __launch_bounds__(256,1)
void scan_persist_kernel(const float* __restrict__ Wr,
                         const float* __restrict__ pbr,
                         const float* __restrict__ pbw)
{
    int bh = blockIdx.x;
    int b = bh >> 2, h = bh & 3;
    int tid = threadIdx.x;

    __shared__ float rv_s[DD];
    __shared__ float ifc_s[256];
    __shared__ float pmat[4][256];
    __shared__ float knr[HDD], knw[HDD];
    __shared__ float simr[NN], simw[NN], swork[NN];
    __shared__ float gr_sh;
    __shared__ float redv[8]; __shared__ int redi[8];
    __shared__ float kv8[TOPKK];
    __shared__ int s_cnt;
    __shared__ int sel_idx[MAXSEL];
    __shared__ float sel_w[MAXSEL];
    __shared__ float s_inv;

    float beta_r = softplus_clip(*pbr);
    float beta_w = softplus_clip(*pbw);

    for (int t=0; t<TT; ++t){
        rv_s[tid] = __ldcg(&g_rvbuf[t&1][b*DD + tid]);
        __syncthreads();
        if (h == 0)
            g_cat[(size_t)(b*TT + t)*KCAT + 512 + tid] = rv_s[tid];

        // iface matvec: float4 loads, 4-way d-split
        {
            int cq = tid & 63, dg = tid >> 6;
            int seg = cq >> 4, cl4 = (cq & 15)*4;
            int col = seg*DD + h*HDD + cl4;
            const float* wp = Wr + (size_t)(dg*64)*IFF + col;
            float ax=0.f, ay=0.f, az=0.f, aw=0.f;
            #pragma unroll 8
            for (int d=0; d<64; ++d){
                float r = rv_s[dg*64 + d];
                float4 w = *reinterpret_cast<const float4*>(wp + (size_t)d*IFF);
                ax += r*w.x; ay += r*w.y; az += r*w.z; aw += r*w.w;
            }
            int p = seg*64 + cl4;
            pmat[dg][p+0]=ax; pmat[dg][p+1]=ay; pmat[dg][p+2]=az; pmat[dg][p+3]=aw;
        }
        if (tid < 32){
            int col = 4*DD + h;
            float acc = 0.f;
            for (int d=tid; d<DD; d+=32) acc += rv_s[d]*Wr[(size_t)d*IFF + col];
            #pragma unroll
            for (int o=16;o>0;o>>=1) acc += __shfl_xor_sync(0xffffffffu, acc, o);
            if (tid==0) gr_sh = acc + g_iface[(size_t)(b*TT + t)*IFF + col];
        }
        __syncthreads();
        {
            int grp = tid >> 6, l = tid & 63;
            int col = grp*DD + h*HDD + l;
            ifc_s[tid] = g_iface[(size_t)(b*TT + t)*IFF + col]
                       + pmat[0][tid] + pmat[1][tid] + pmat[2][tid] + pmat[3][tid];
        }
        __syncthreads();

        // normalize keys
        if (tid < 64){
            int w = tid >> 5, l = tid & 31;
            float v0 = ifc_s[w*64 + l], v1 = ifc_s[w*64 + l + 32];
            float ss = v0*v0 + v1*v1;
            #pragma unroll
            for (int o=16;o>0;o>>=1) ss += __shfl_xor_sync(0xffffffffu, ss, o);
            float rn = rsqrtf(ss + 1e-8f);
            float* dst = w ? knw : knr;
            dst[l] = v0*rn; dst[l+32] = v1*rn;
        }
        __syncthreads();

        // sims
        {
            int warp = tid >> 5, lane = tid & 31;
            int oct = lane >> 3, r = lane & 7;
            float4 kr0 = *(const float4*)&knr[r*8], kr1 = *(const float4*)&knr[r*8+4];
            float4 kw0 = *(const float4*)&knw[r*8], kw1 = *(const float4*)&knw[r*8+4];
            for (int it=0; it<NN/32; ++it){
                int n = it*32 + warp*4 + oct;
                const float* mrow = g_mem + (((size_t)b*NN + n)*HMM + h)*HDD + r*8;
                float4 m0 = *(const float4*)mrow, m1 = *(const float4*)(mrow+4);
                float ss = m0.x*m0.x+m0.y*m0.y+m0.z*m0.z+m0.w*m0.w
                         + m1.x*m1.x+m1.y*m1.y+m1.z*m1.z+m1.w*m1.w;
                float dr = m0.x*kr0.x+m0.y*kr0.y+m0.z*kr0.z+m0.w*kr0.w
                         + m1.x*kr1.x+m1.y*kr1.y+m1.z*kr1.z+m1.w*kr1.w;
                float dw = m0.x*kw0.x+m0.y*kw0.y+m0.z*kw0.z+m0.w*kw0.w
                         + m1.x*kw1.x+m1.y*kw1.y+m1.z*kw1.z+m1.w*kw1.w;
                #pragma unroll
                for (int o=4;o>0;o>>=1){
                    ss += __shfl_xor_sync(0xffffffffu, ss, o);
                    dr += __shfl_xor_sync(0xffffffffu, dr, o);
                    dw += __shfl_xor_sync(0xffffffffu, dw, o);
                }
                if (r == 0){
                    float rn = rsqrtf(ss + 1e-8f);
                    simr[n] = dr*rn;
                    simw[n] = dw*rn;
                }
            }
        }
        __syncthreads();

        for (int phase=0; phase<2; ++phase){
            float beta = phase ? beta_w : beta_r;
            float* sim = phase ? simw : simr;
            for (int i=tid;i<NN;i+=256) swork[i]=sim[i];
            if (tid==0) s_cnt = 0;
            __syncthreads();
            for (int it=0; it<TOPKK; ++it){
                float bv = -3.4e38f; int bi = 0;
                #pragma unroll
                for (int j=0;j<NN/256;j++){
                    int i = tid + j*256;
                    float v = swork[i];
                    if (v > bv){ bv=v; bi=i; }
                }
                #pragma unroll
                for (int o=16;o>0;o>>=1){
                    float ov = __shfl_xor_sync(0xffffffffu, bv, o);
                    int   oi = __shfl_xor_sync(0xffffffffu, bi, o);
                    if (ov > bv){ bv=ov; bi=oi; }
                }
                if ((tid&31)==0){ redv[tid>>5]=bv; redi[tid>>5]=bi; }
                __syncthreads();
                if (tid==0){
                    float m = redv[0]; int mi = redi[0];
                    #pragma unroll
                    for (int w=1;w<8;w++) if (redv[w]>m){ m=redv[w]; mi=redi[w]; }
                    kv8[it]=m; swork[mi] = -3.4e38f;
                }
                __syncthreads();
            }
            float kth = kv8[TOPKK-1], smax = kv8[0];
            for (int i=tid;i<NN;i+=256){
                float v = sim[i];
                if (v >= kth){
                    int p = atomicAdd(&s_cnt, 1);
                    if (p < MAXSEL){ sel_idx[p]=i; sel_w[p]=expf(beta*(v-smax)); }
                }
            }
            __syncthreads();
            int cnt = min(s_cnt, MAXSEL);
            if (tid==0){
                float ds=0.f;
                for (int j=0;j<cnt;j++) ds += sel_w[j];
                s_inv = 1.0f/ds;
            }
            __syncthreads();
            float invd = s_inv;
            if (phase==0){
                if (tid < HDD){
                    float acc=0.f;
                    for (int j=0;j<cnt;j++)
                        acc += sel_w[j]*invd * g_mem[(((size_t)b*NN + sel_idx[j])*HMM + h)*HDD + tid];
                    __stcg(&g_rvbuf[(t+1)&1][b*DD + h*HDD + tid], acc);
                }
                __syncthreads();
                if (tid==0){
                    __threadfence();
                    atomicAdd(&g_bar[b], 1u);
                }
            } else {
                float gg = sigmoid_f(gr_sh);
                int d = tid & 63;
                float ee = sigmoid_f(ifc_s[192 + d]);
                float gv = gg * ifc_s[128 + d];
                for (int j = tid>>6; j<cnt; j+=4){
                    float w = sel_w[j]*invd;
                    size_t mi = (((size_t)b*NN + sel_idx[j])*HMM + h)*HDD + d;
                    g_mem[mi] = g_mem[mi]*(1.0f - w*ee) + w*gv;
                }
            }
            __syncthreads();
        }

        if (tid==0){
            while (atomicAdd(&g_bar[b], 0u) < 4u*(unsigned)(t+1)) { }
        }
        __syncthreads();
    }
}

extern "C" void kernel_launch(void* const* d_in, const int* in_sizes, int n_in,
                              void* d_out, int out_size)
{
    const int*   ids      = (const int*)  d_in[0];
    const float* emb      = (const float*)d_in[1];
    const float* pos      = (const float*)d_in[2];
    const float* ln1_g    = (const float*)d_in[3];
    const float* ln1_b    = (const float*)d_in[4];
    const float* ln2_g    = (const float*)d_in[5];
    const float* ln2_b    = (const float*)d_in[6];
    const float* Wq       = (const float*)d_in[7];
    const float* Wk       = (const float*)d_in[8];
    const float* Wv       = (const float*)d_in[9];
    const float* Wo       = (const float*)d_in[10];
    const float* W1       = (const float*)d_in[11];
    const float* b1       = (const float*)d_in[12];
    const float* W2       = (const float*)d_in[13];
    const float* b2       = (const float*)d_in[14];
    const float* lnf_g    = (const float*)d_in[15];
    const float* lnf_b    = (const float*)d_in[16];
    const float* W_if_h   = (const float*)d_in[17];
    const float* W_if_r   = (const float*)d_in[18];
    const float* b_if     = (const float*)d_in[19];
    const float* W_lg_h   = (const float*)d_in[20];
    const float* W_lg_r   = (const float*)d_in[21];
    const float* b_lg     = (const float*)d_in[22];
    const float* beta_read  = (const float*)d_in[23];
    const float* beta_write = (const float*)d_in[24];
    const float* mem_init = (const float*)d_in[25];
    float* out = (float*)d_out;

    float *px,*phh,*pq,*pk,*pv,*po,*pu,*pif,*pcat;
    u32 *pwh,*pwl,*pah,*pal;
    cudaGetSymbolAddress((void**)&px,  g_x);
    cudaGetSymbolAddress((void**)&phh, g_h);
    cudaGetSymbolAddress((void**)&pq,  g_q);
    cudaGetSymbolAddress((void**)&pk,  g_k);
    cudaGetSymbolAddress((void**)&pv,  g_v);
    cudaGetSymbolAddress((void**)&po,  g_o);
    cudaGetSymbolAddress((void**)&pu,  g_u);
    cudaGetSymbolAddress((void**)&pif, g_iface);
    cudaGetSymbolAddress((void**)&pcat,g_cat);
    cudaGetSymbolAddress((void**)&pwh, g_wh);
    cudaGetSymbolAddress((void**)&pwl, g_wl);
    cudaGetSymbolAddress((void**)&pah, g_ah);
    cudaGetSymbolAddress((void**)&pal, g_al);

    const int M = BB*TT;

    // weight splits
    const float* qkvo[4] = {Wq, Wk, Wv, Wo};
    for (int l=0;l<LL;l++){
        for (int w=0;w<4;w++)
            wsplit_kernel<<<dim3(2,256),256>>>(qkvo[w] + (size_t)l*EE*EE,
                pwh + OFF_QKVO(l,w), pwl + OFF_QKVO(l,w), EE);
        wsplit_kernel<<<dim3(8,256),256>>>(W1 + (size_t)l*EE*FF, pwh + OFF_W1(l), pwl + OFF_W1(l), FF);
        wsplit_kernel<<<dim3(2,1024),256>>>(W2 + (size_t)l*FF*EE, pwh + OFF_W2(l), pwl + OFF_W2(l), EE);
    }
    wsplit_kernel<<<dim3(5,256),256>>>(W_if_h, pwh + OFF_WIFH, pwl + OFF_WIFH, IFF);
    wsplit_kernel<<<dim3(125,256),256>>>(W_lg_h, pwh + OFF_WLG, pwl + OFF_WLG, VV);
    wsplit_kernel<<<dim3(125,128),256>>>(W_lg_r, pwh + OFF_WLG + (size_t)256*VV,
                                         pwl + OFF_WLG + (size_t)256*VV, VV);

    embed_kernel<<<M,256>>>(ids, emb, pos);

    for (int l=0; l<LL; ++l){
        ln_kernel<<<M,256>>>(px, ln1_g + l*EE, ln1_b + l*EE, phh, EE);
        asplit_kernel<<<M,256>>>(phh, EE, pah, pal, 256, 0, 256);
        bgemm_kernel<false,false,false,false><<<dim3(4,16),256>>>(pah, pal, 256,
            pwh+OFF_QKVO(l,0), pwl+OFF_QKVO(l,0), nullptr, pq, EE, 256);
        bgemm_kernel<false,false,false,false><<<dim3(4,16),256>>>(pah, pal, 256,
            pwh+OFF_QKVO(l,1), pwl+OFF_QKVO(l,1), nullptr, pk, EE, 256);
        bgemm_kernel<false,false,false,false><<<dim3(4,16),256>>>(pah, pal, 256,
            pwh+OFF_QKVO(l,2), pwl+OFF_QKVO(l,2), nullptr, pv, EE, 256);
        attn_s_kernel<<<dim3(64, BB*HAA),256>>>();
        softmax_kernel<<<BB*HAA*TT,256>>>();
        attn_o_kernel<<<dim3(8, BB*HAA),256>>>();
        asplit_kernel<<<M,256>>>(po, EE, pah, pal, 256, 0, 256);
        bgemm_kernel<true,false,false,false><<<dim3(4,16),256>>>(pah, pal, 256,
            pwh+OFF_QKVO(l,3), pwl+OFF_QKVO(l,3), nullptr, px, EE, 256);
        ln_kernel<<<M,256>>>(px, ln2_g + l*EE, ln2_b + l*EE, phh, EE);
        asplit_kernel<<<M,256>>>(phh, EE, pah, pal, 256, 0, 256);
        bgemm_kernel<false,true,true,false><<<dim3(16,16),256>>>(pah, pal, 256,
            pwh+OFF_W1(l), pwl+OFF_W1(l), b1 + l*FF, pu, FF, 256);
        asplit_kernel<<<M,256>>>(pu, FF, pah, pal, 1024, 0, 1024);
        bgemm_kernel<true,false,true,false><<<dim3(4,16),256>>>(pah, pal, 1024,
            pwh+OFF_W2(l), pwl+OFF_W2(l), b2 + l*EE, px, EE, 1024);
    }

    // final LN -> g_cat cols [0,512); split h-part into planes (lda2=384)
    ln_kernel<<<M,256>>>(px, lnf_g, lnf_b, pcat, KCAT);
    asplit_kernel<<<M,256>>>(pcat, KCAT, pah, pal, 384, 0, 256);

    // iface = h @ W_if_h + b_if
    bgemm_kernel<false,false,true,true><<<dim3(9,16),256>>>(pah, pal, 384,
        pwh+OFF_WIFH, pwl+OFF_WIFH, b_if, pif, IFF, 256);

    meminit_kernel<<<16384,256>>>(mem_init);
    scaninit_kernel<<<8,256>>>();

    scan_persist_kernel<<<BB*HMM,256>>>(W_if_r, beta_read, beta_write);

    // split rv-carry part (cols 512..767) into planes kp 256..383
    asplit_kernel<<<M,256>>>(pcat + 512, KCAT, pah, pal, 384, 256, 128);

    // out = [h | rv] @ [W_lg_h ; W_lg_r] + b_lg
    bgemm_kernel<false,false,true,false><<<dim3(250,16),256>>>(pah, pal, 384,
        pwh+OFF_WLG, pwl+OFF_WLG, b_lg, out, VV, 384);
}

// round 8
// speedup vs baseline: 1.4545x; 1.0356x over previous
#include <cuda_runtime.h>
#include <math.h>

typedef unsigned int u32;

#define BB 8
#define TT 256
#define EE 512
#define FF 2048
#define DD 256
#define NN 2048
#define LL 2
#define VV 32000
#define HMM 4
#define HDD 64
#define HAA 8
#define DHH 64
#define IFF 1028
#define TOPKK 8
#define MAXSEL 64
#define KCAT 768

// weight-plane arena offsets (u32 units)
#define OFF_QKVO(l,w) (((l)*4+(w))*131072)
#define OFF_W1(l) (1048576 + (l)*524288)
#define OFF_W2(l) (2097152 + (l)*524288)
#define OFF_WIFH 3145728
#define OFF_WLG  3408896
#define ARENA    15696896

// ---- scratch ----
__device__ float g_x[BB*TT*EE];
__device__ float g_h[BB*TT*EE];
__device__ float g_q[BB*TT*EE];
__device__ float g_k[BB*TT*EE];
__device__ float g_v[BB*TT*EE];
__device__ float g_o[BB*TT*EE];
__device__ float g_s[BB*HAA*TT*TT];
__device__ float g_u[BB*TT*FF];
__device__ float g_iface[BB*TT*IFF];
__device__ float g_mem[BB*NN*HMM*HDD];
__device__ float g_cat[BB*TT*KCAT];
__device__ float g_rvbuf[2][BB*DD];
__device__ u32   g_bar[BB];
__device__ u32   g_wh[ARENA];
__device__ u32   g_wl[ARENA];
__device__ u32   g_ah[2048*1024];
__device__ u32   g_al[2048*1024];

__device__ __forceinline__ float gelu_f(float x){
    float x3 = x*x*x;
    return 0.5f*x*(1.0f+tanhf(0.7978845608028654f*(x+0.044715f*x3)));
}
__device__ __forceinline__ float sigmoid_f(float x){ return 1.0f/(1.0f+expf(-x)); }
__device__ __forceinline__ float softplus_clip(float x){
    float sp = fmaxf(x,0.0f) + log1pf(expf(-fabsf(x)));
    return fminf(fmaxf(sp,1.0f),20.0f);
}

__device__ __forceinline__ void packpair(float e, float o, u32 &hi, u32 &lo){
    u32 h; asm("cvt.rn.bf16x2.f32 %0, %1, %2;" : "=r"(h) : "f"(o), "f"(e));
    float he = __uint_as_float(h<<16);
    float ho = __uint_as_float(h & 0xffff0000u);
    asm("cvt.rn.bf16x2.f32 %0, %1, %2;" : "=r"(lo) : "f"(o-ho), "f"(e-he));
    hi = h;
}

__device__ __forceinline__ void mma_bf16(float* c, const u32* a, const u32* b){
    asm volatile("mma.sync.aligned.m16n8k16.row.col.f32.bf16.bf16.f32 "
        "{%0,%1,%2,%3}, {%4,%5,%6,%7}, {%8,%9}, {%0,%1,%2,%3};\n"
        : "+f"(c[0]), "+f"(c[1]), "+f"(c[2]), "+f"(c[3])
        : "r"(a[0]), "r"(a[1]), "r"(a[2]), "r"(a[3]), "r"(b[0]), "r"(b[1]));
}

__device__ __forceinline__ u32 s2u(const void* p){ return (u32)__cvta_generic_to_shared(p); }
__device__ __forceinline__ void cp16(u32 d, const void* s){
    asm volatile("cp.async.cg.shared.global [%0], [%1], 16;\n"::"r"(d),"l"(s));
}
__device__ __forceinline__ void cp16z(u32 d, const void* s, int sz){
    asm volatile("cp.async.cg.shared.global [%0], [%1], 16, %2;\n"::"r"(d),"l"(s),"r"(sz));
}
__device__ __forceinline__ void cp_commit(){ asm volatile("cp.async.commit_group;\n"); }
__device__ __forceinline__ void cp_wait0(){ asm volatile("cp.async.wait_group 0;\n"); }

// ---- weight split: f32 [K][N] -> hi/lo u32 planes [K/2][N] ----
__global__ void wsplit_kernel(const float* __restrict__ src, u32* __restrict__ dh,
                              u32* __restrict__ dl, int N){
    int k2 = blockIdx.y;
    int n = blockIdx.x*256 + threadIdx.x;
    if (n >= N) return;
    float e = src[(size_t)(2*k2)*N + n];
    float o = src[(size_t)(2*k2+1)*N + n];
    u32 hi, lo; packpair(e, o, hi, lo);
    dh[(size_t)k2*N + n] = hi;
    dl[(size_t)k2*N + n] = lo;
}

// ---- activation split ----
__global__ void asplit_kernel(const float* __restrict__ src, int lds,
                              u32* __restrict__ dh, u32* __restrict__ dl,
                              int lda2, int kpo, int nkp){
    int row = blockIdx.x;
    for (int kp = threadIdx.x; kp < nkp; kp += 256){
        float e = src[(size_t)row*lds + 2*kp];
        float o = src[(size_t)row*lds + 2*kp + 1];
        u32 hi, lo; packpair(e, o, hi, lo);
        dh[(size_t)row*lda2 + kpo + kp] = hi;
        dl[(size_t)row*lda2 + kpo + kp] = lo;
    }
}

// ---- embedding ----
__global__ void embed_kernel(const int* __restrict__ ids,
                             const float* __restrict__ emb,
                             const float* __restrict__ pos){
    int bt = blockIdx.x;
    int t = bt & (TT-1);
    int id = ids[bt];
    for (int e = threadIdx.x; e < EE; e += 256)
        g_x[(size_t)bt*EE + e] = emb[(size_t)id*EE + e] + pos[(size_t)t*EE + e];
}

// ---- layernorm ----
__global__ void ln_kernel(const float* __restrict__ x, const float* __restrict__ g,
                          const float* __restrict__ bb, float* __restrict__ out, int ostride){
    int row = blockIdx.x, tid = threadIdx.x;
    __shared__ float red[256];
    const float* xr = x + (size_t)row*EE;
    float v0 = xr[tid], v1 = xr[tid+256];
    red[tid] = v0+v1; __syncthreads();
    for (int s=128;s>0;s>>=1){ if (tid<s) red[tid]+=red[tid+s]; __syncthreads(); }
    float m = red[0] * (1.0f/EE);
    __syncthreads();
    float d0=v0-m, d1=v1-m;
    red[tid] = d0*d0 + d1*d1; __syncthreads();
    for (int s=128;s>0;s>>=1){ if (tid<s) red[tid]+=red[tid+s]; __syncthreads(); }
    float rs = rsqrtf(red[0]*(1.0f/EE) + 1e-5f);
    out[(size_t)row*ostride + tid]       = d0*rs*g[tid]     + bb[tid];
    out[(size_t)row*ostride + tid + 256] = d1*rs*g[tid+256] + bb[tid+256];
}

// ---- bf16x3 tensor GEMM with cp.async double-buffer pipeline ----
// A planes m-major in smem with 12-u32 row stride (16B-aligned, conflict-free LDS).
template<bool ACC, bool GELU, bool BIAS, bool NGUARD>
__global__ __launch_bounds__(256,1)
void bgemm_kernel(const u32* __restrict__ AH, const u32* __restrict__ AL, int lda2,
                  const u32* __restrict__ BH, const u32* __restrict__ BL,
                  const float* __restrict__ bias, float* __restrict__ C,
                  int N, int K2)
{
    __shared__ u32 AsH[2][128*12], AsL[2][128*12];
    __shared__ u32 BsH[2][8][136], BsL[2][8][136];
    int tid = threadIdx.x;
    int bm = blockIdx.y*128, bn = blockIdx.x*128;
    int warp = tid>>5, lane = tid&31;
    int wm = (warp>>2)*64, wn = (warp&3)*32;
    int gid = lane>>2, tig = lane&3;

    float c[4][4][4];
    #pragma unroll
    for (int mt=0;mt<4;mt++)
        #pragma unroll
        for (int nt=0;nt<4;nt++)
            #pragma unroll
            for (int i=0;i<4;i++) c[mt][nt][i]=0.f;

    int am = tid & 127, akp = (tid>>7)*4;
    int bk = tid>>5, bn4 = lane*4;
    const u32* AHp = AH + (size_t)(bm+am)*lda2 + akp;
    const u32* ALp = AL + (size_t)(bm+am)*lda2 + akp;
    int nit = K2/8;

    auto issueTile = [&](int buf, int it){
        cp16(s2u(&AsH[buf][am*12+akp]), AHp + (size_t)it*8);
        cp16(s2u(&AsL[buf][am*12+akp]), ALp + (size_t)it*8);
        int kr = it*8 + bk;
        const u32* ph_ = BH + (size_t)kr*N + bn + bn4;
        const u32* pl_ = BL + (size_t)kr*N + bn + bn4;
        if (!NGUARD){
            cp16(s2u(&BsH[buf][bk][bn4]), ph_);
            cp16(s2u(&BsL[buf][bk][bn4]), pl_);
        } else {
            int col = bn + bn4;
            int sz = (N - col)*4; sz = sz<0?0:(sz>16?16:sz);
            cp16z(s2u(&BsH[buf][bk][bn4]), ph_, sz);
            cp16z(s2u(&BsL[buf][bk][bn4]), pl_, sz);
        }
    };

    issueTile(0, 0); cp_commit();

    int cur = 0;
    for (int it=0; it<nit; ++it){
        cp_wait0();
        __syncthreads();
        if (it+1 < nit){ issueTile(cur^1, it+1); cp_commit(); }

        u32 aH[4][4], aL[4][4];
        #pragma unroll
        for (int mt=0;mt<4;mt++){
            int m0 = wm + mt*16 + gid;
            aH[mt][0]=AsH[cur][m0*12     + tig  ]; aL[mt][0]=AsL[cur][m0*12     + tig  ];
            aH[mt][1]=AsH[cur][(m0+8)*12 + tig  ]; aL[mt][1]=AsL[cur][(m0+8)*12 + tig  ];
            aH[mt][2]=AsH[cur][m0*12     + tig+4]; aL[mt][2]=AsL[cur][m0*12     + tig+4];
            aH[mt][3]=AsH[cur][(m0+8)*12 + tig+4]; aL[mt][3]=AsL[cur][(m0+8)*12 + tig+4];
        }
        u32 bH[4][2], bL[4][2];
        #pragma unroll
        for (int nt=0;nt<4;nt++){
            int n0 = wn + nt*8 + gid;
            bH[nt][0]=BsH[cur][tig  ][n0]; bL[nt][0]=BsL[cur][tig  ][n0];
            bH[nt][1]=BsH[cur][tig+4][n0]; bL[nt][1]=BsL[cur][tig+4][n0];
        }
        #pragma unroll
        for (int mt=0;mt<4;mt++){
            #pragma unroll
            for (int nt=0;nt<4;nt++){
                mma_bf16(c[mt][nt], aH[mt], bH[nt]);
                mma_bf16(c[mt][nt], aH[mt], bL[nt]);
                mma_bf16(c[mt][nt], aL[mt], bH[nt]);
            }
        }
        cur ^= 1;
    }

    #pragma unroll
    for (int mt=0;mt<4;mt++){
        int ra = bm + wm + mt*16 + gid;
        int rb = ra + 8;
        #pragma unroll
        for (int nt=0;nt<4;nt++){
            int col = bn + wn + nt*8 + tig*2;
            #pragma unroll
            for (int q=0;q<4;q++){
                int r = (q<2)? ra : rb;
                int cc = col + (q&1);
                if (NGUARD && cc >= N) continue;
                float v = c[mt][nt][q];
                if (BIAS) v += bias[cc];
                if (GELU) v = gelu_f(v);
                size_t idx = (size_t)r*N + cc;
                if (ACC) v += C[idx];
                C[idx] = v;
            }
        }
    }
}

// ---- attention ----
__global__ void attn_s_kernel(){
    int bh = blockIdx.y;
    int b = bh >> 3, h = bh & 7;
    int qt = blockIdx.x >> 3, kt = blockIdx.x & 7;
    __shared__ float Qs[32][65];
    __shared__ float Ks[32][65];
    int tid = threadIdx.x;
    {
        int r = tid >> 3, cc = (tid & 7)*8;
        const float* qsrc = g_q + ((size_t)(b*TT + qt*32 + r))*EE + h*DHH + cc;
        const float* ksrc = g_k + ((size_t)(b*TT + kt*32 + r))*EE + h*DHH + cc;
        float4 q0 = *(const float4*)qsrc, q1 = *(const float4*)(qsrc+4);
        float4 k0 = *(const float4*)ksrc, k1 = *(const float4*)(ksrc+4);
        Qs[r][cc+0]=q0.x; Qs[r][cc+1]=q0.y; Qs[r][cc+2]=q0.z; Qs[r][cc+3]=q0.w;
        Qs[r][cc+4]=q1.x; Qs[r][cc+5]=q1.y; Qs[r][cc+6]=q1.z; Qs[r][cc+7]=q1.w;
        Ks[r][cc+0]=k0.x; Ks[r][cc+1]=k0.y; Ks[r][cc+2]=k0.z; Ks[r][cc+3]=k0.w;
        Ks[r][cc+4]=k1.x; Ks[r][cc+5]=k1.y; Ks[r][cc+6]=k1.z; Ks[r][cc+7]=k1.w;
    }
    __syncthreads();
    int r = tid & 31, gq = tid >> 5;
    float a0=0,a1=0,a2=0,a3=0;
    #pragma unroll
    for (int kk=0;kk<64;kk++){
        float qv = Qs[r][kk];
        a0 += qv*Ks[gq*4+0][kk];
        a1 += qv*Ks[gq*4+1][kk];
        a2 += qv*Ks[gq*4+2][kk];
        a3 += qv*Ks[gq*4+3][kk];
    }
    int qrow = qt*32 + r;
    int kc = kt*32 + gq*4;
    float* srow = g_s + ((size_t)bh*TT + qrow)*TT + kc;
    srow[0] = (kc+0<=qrow)? a0*0.125f : -1e30f;
    srow[1] = (kc+1<=qrow)? a1*0.125f : -1e30f;
    srow[2] = (kc+2<=qrow)? a2*0.125f : -1e30f;
    srow[3] = (kc+3<=qrow)? a3*0.125f : -1e30f;
}

__global__ void softmax_kernel(){
    int row = blockIdx.x, tid = threadIdx.x;
    __shared__ float red[256];
    float* sp = g_s + (size_t)row*TT;
    float v = sp[tid];
    red[tid]=v; __syncthreads();
    for (int s=128;s>0;s>>=1){ if (tid<s) red[tid]=fmaxf(red[tid],red[tid+s]); __syncthreads(); }
    float m = red[0]; __syncthreads();
    float e = expf(v-m);
    red[tid]=e; __syncthreads();
    for (int s=128;s>0;s>>=1){ if (tid<s) red[tid]+=red[tid+s]; __syncthreads(); }
    sp[tid] = e / red[0];
}

__global__ void attn_o_kernel(){
    int bh = blockIdx.y;
    int b = bh >> 3, h = bh & 7;
    int qt = blockIdx.x;
    __shared__ float As[32][65];
    __shared__ float Vs[64][64];
    int tid = threadIdx.x;
    int d = tid & 63, qg = tid >> 6;
    float acc[8];
    #pragma unroll
    for (int i=0;i<8;i++) acc[i]=0.f;
    for (int k0=0;k0<TT;k0+=64){
        {
            int r = tid >> 3, cc = (tid & 7)*8;
            const float* src = g_s + ((size_t)bh*TT + qt*32 + r)*TT + k0 + cc;
            float4 a0=*(const float4*)src, a1=*(const float4*)(src+4);
            As[r][cc+0]=a0.x; As[r][cc+1]=a0.y; As[r][cc+2]=a0.z; As[r][cc+3]=a0.w;
            As[r][cc+4]=a1.x; As[r][cc+5]=a1.y; As[r][cc+6]=a1.z; As[r][cc+7]=a1.w;
        }
        #pragma unroll
        for (int i=0;i<4;i++){
            int fl = (tid + 256*i)*4;
            int r = fl >> 6, cc = fl & 63;
            float4 vv = *(const float4*)(g_v + ((size_t)(b*TT + k0 + r))*EE + h*DHH + cc);
            *(float4*)&Vs[r][cc] = vv;
        }
        __syncthreads();
        #pragma unroll
        for (int kk=0;kk<64;kk++){
            float vv = Vs[kk][d];
            #pragma unroll
            for (int i=0;i<8;i++) acc[i] += As[qg*8+i][kk]*vv;
        }
        __syncthreads();
    }
    #pragma unroll
    for (int i=0;i<8;i++){
        int qr = qt*32 + qg*8 + i;
        g_o[((size_t)(b*TT + qr))*EE + h*DHH + d] = acc[i];
    }
}

// ---- init ----
__global__ void meminit_kernel(const float* __restrict__ mi){
    int idx = blockIdx.x*256 + threadIdx.x;
    g_mem[idx] = mi[idx & (NN*DD - 1)];
}
__global__ void scaninit_kernel(){
    int i = blockIdx.x*256 + threadIdx.x;
    g_rvbuf[0][i] = 0.f;
    if (i < BB) g_bar[i] = 0u;
}

// ---- persistent fused scan with warp-parallel topk ----
__global__ __launch_bounds__(256,1)
void scan_persist_kernel(const float* __restrict__ Wr,
                         const float* __restrict__ pbr,
                         const float* __restrict__ pbw)
{
    int bh = blockIdx.x;
    int b = bh >> 2, h = bh & 3;
    int tid = threadIdx.x, warp = tid>>5, lane = tid&31;

    __shared__ float rv_s[DD];
    __shared__ float ifc_s[256];
    __shared__ float pmat[4][256];
    __shared__ float knr[HDD], knw[HDD];
    __shared__ float simr[NN], simw[NN];
    __shared__ float gr_sh;
    __shared__ float candv[2][32];
    __shared__ float s_kth[2], s_smax[2];
    __shared__ int   s_cnt[2];
    __shared__ int   sel_idx[2][MAXSEL];
    __shared__ float sel_w[2][MAXSEL];
    __shared__ float s_inv[2];

    float beta_r = softplus_clip(*pbr);
    float beta_w = softplus_clip(*pbw);

    for (int t=0; t<TT; ++t){
        rv_s[tid] = __ldcg(&g_rvbuf[t&1][b*DD + tid]);
        if (tid==0){ s_cnt[0]=0; s_cnt[1]=0; }
        __syncthreads();
        if (h == 0)
            g_cat[(size_t)(b*TT + t)*KCAT + 512 + tid] = rv_s[tid];

        // iface matvec: float4 loads, 4-way d-split
        {
            int cq = tid & 63, dg = tid >> 6;
            int seg = cq >> 4, cl4 = (cq & 15)*4;
            int col = seg*DD + h*HDD + cl4;
            const float* wp = Wr + (size_t)(dg*64)*IFF + col;
            float ax=0.f, ay=0.f, az=0.f, aw=0.f;
            #pragma unroll 8
            for (int d=0; d<64; ++d){
                float r = rv_s[dg*64 + d];
                float4 w = *reinterpret_cast<const float4*>(wp + (size_t)d*IFF);
                ax += r*w.x; ay += r*w.y; az += r*w.z; aw += r*w.w;
            }
            int p = seg*64 + cl4;
            pmat[dg][p+0]=ax; pmat[dg][p+1]=ay; pmat[dg][p+2]=az; pmat[dg][p+3]=aw;
        }
        if (tid < 32){
            int col = 4*DD + h;
            float acc = 0.f;
            for (int d=tid; d<DD; d+=32) acc += rv_s[d]*Wr[(size_t)d*IFF + col];
            #pragma unroll
            for (int o=16;o>0;o>>=1) acc += __shfl_xor_sync(0xffffffffu, acc, o);
            if (tid==0) gr_sh = acc + g_iface[(size_t)(b*TT + t)*IFF + col];
        }
        __syncthreads();
        {
            int grp = tid >> 6, l = tid & 63;
            int col = grp*DD + h*HDD + l;
            ifc_s[tid] = g_iface[(size_t)(b*TT + t)*IFF + col]
                       + pmat[0][tid] + pmat[1][tid] + pmat[2][tid] + pmat[3][tid];
        }
        __syncthreads();

        // normalize keys
        if (tid < 64){
            int w = tid >> 5, l = tid & 31;
            float v0 = ifc_s[w*64 + l], v1 = ifc_s[w*64 + l + 32];
            float ss = v0*v0 + v1*v1;
            #pragma unroll
            for (int o=16;o>0;o>>=1) ss += __shfl_xor_sync(0xffffffffu, ss, o);
            float rn = rsqrtf(ss + 1e-8f);
            float* dst = w ? knw : knr;
            dst[l] = v0*rn; dst[l+32] = v1*rn;
        }
        __syncthreads();

        // sims
        {
            int oct = lane >> 3, r = lane & 7;
            float4 kr0 = *(const float4*)&knr[r*8], kr1 = *(const float4*)&knr[r*8+4];
            float4 kw0 = *(const float4*)&knw[r*8], kw1 = *(const float4*)&knw[r*8+4];
            for (int it=0; it<NN/32; ++it){
                int n = it*32 + warp*4 + oct;
                const float* mrow = g_mem + (((size_t)b*NN + n)*HMM + h)*HDD + r*8;
                float4 m0 = *(const float4*)mrow, m1 = *(const float4*)(mrow+4);
                float ss = m0.x*m0.x+m0.y*m0.y+m0.z*m0.z+m0.w*m0.w
                         + m1.x*m1.x+m1.y*m1.y+m1.z*m1.z+m1.w*m1.w;
                float dr = m0.x*kr0.x+m0.y*kr0.y+m0.z*kr0.z+m0.w*kr0.w
                         + m1.x*kr1.x+m1.y*kr1.y+m1.z*kr1.z+m1.w*kr1.w;
                float dw = m0.x*kw0.x+m0.y*kw0.y+m0.z*kw0.z+m0.w*kw0.w
                         + m1.x*kw1.x+m1.y*kw1.y+m1.z*kw1.z+m1.w*kw1.w;
                #pragma unroll
                for (int o=4;o>0;o>>=1){
                    ss += __shfl_xor_sync(0xffffffffu, ss, o);
                    dr += __shfl_xor_sync(0xffffffffu, dr, o);
                    dw += __shfl_xor_sync(0xffffffffu, dw, o);
                }
                if (r == 0){
                    float rn = rsqrtf(ss + 1e-8f);
                    simr[n] = dr*rn;
                    simw[n] = dw*rn;
                }
            }
        }
        __syncthreads();

        // warp-parallel topk: warps 0-3 read-phase, warps 4-7 write-phase
        {
            int ph = warp >> 2, wi = warp & 3;
            const float* sim = ph ? simw : simr;
            float lv[16];
            #pragma unroll
            for (int j=0;j<16;j++) lv[j] = sim[wi*512 + j*32 + lane];
            #pragma unroll
            for (int it=0; it<TOPKK; ++it){
                float m=-3.4e38f; int mi=0;
                #pragma unroll
                for (int j=0;j<16;j++) if (lv[j]>m){ m=lv[j]; mi=j; }
                float bm=m; int bl=lane;
                #pragma unroll
                for (int o=16;o>0;o>>=1){
                    float om=__shfl_xor_sync(0xffffffffu,bm,o);
                    int   ol=__shfl_xor_sync(0xffffffffu,bl,o);
                    if (om>bm || (om==bm && ol<bl)){ bm=om; bl=ol; }
                }
                if (lane==bl) lv[mi] = -3.4e38f;
                if (lane==0) candv[ph][wi*8+it] = bm;
            }
        }
        __syncthreads();
        if ((warp&3)==0){
            int ph = warp>>2;
            float v = candv[ph][lane];
            float kth_=0.f, smax_=0.f;
            #pragma unroll
            for (int it=0; it<TOPKK; ++it){
                float bm=v; int bl=lane;
                #pragma unroll
                for (int o=16;o>0;o>>=1){
                    float om=__shfl_xor_sync(0xffffffffu,bm,o);
                    int   ol=__shfl_xor_sync(0xffffffffu,bl,o);
                    if (om>bm || (om==bm && ol<bl)){ bm=om; bl=ol; }
                }
                if (it==0) smax_=bm;
                if (it==TOPKK-1) kth_=bm;
                if (lane==bl) v = -3.4e38f;
            }
            if (lane==0){ s_kth[ph]=kth_; s_smax[ph]=smax_; }
        }
        __syncthreads();

        // selection: tid<128 -> read phase, tid>=128 -> write phase
        {
            int ph = tid >> 7, lt = tid & 127;
            const float* sim = ph ? simw : simr;
            float kth = s_kth[ph], smax = s_smax[ph];
            float beta = ph ? beta_w : beta_r;
            #pragma unroll
            for (int j=0;j<16;j++){
                int i = j*128 + lt;
                float v = sim[i];
                if (v >= kth){
                    int p = atomicAdd(&s_cnt[ph], 1);
                    if (p < MAXSEL){ sel_idx[ph][p]=i; sel_w[ph][p]=expf(beta*(v-smax)); }
                }
            }
        }
        __syncthreads();
        if (tid < 2){
            int cnt = min(s_cnt[tid], MAXSEL);
            float ds=0.f;
            for (int j=0;j<cnt;j++) ds += sel_w[tid][j];
            s_inv[tid] = 1.0f/ds;
        }
        __syncthreads();

        // read gather (must complete before write update touches mem)
        {
            int cnt = min(s_cnt[0], MAXSEL);
            if (tid < HDD){
                float acc=0.f;
                float invd = s_inv[0];
                for (int j=0;j<cnt;j++)
                    acc += sel_w[0][j]*invd * g_mem[(((size_t)b*NN + sel_idx[0][j])*HMM + h)*HDD + tid];
                __stcg(&g_rvbuf[(t+1)&1][b*DD + h*HDD + tid], acc);
            }
        }
        __syncthreads();
        if (tid==0){
            __threadfence();
            atomicAdd(&g_bar[b], 1u);
        }

        // write update
        {
            int cnt = min(s_cnt[1], MAXSEL);
            float gg = sigmoid_f(gr_sh);
            int d = tid & 63;
            float ee = sigmoid_f(ifc_s[192 + d]);
            float gv = gg * ifc_s[128 + d];
            float invd = s_inv[1];
            for (int j = tid>>6; j<cnt; j+=4){
                float w = sel_w[1][j]*invd;
                size_t mi = (((size_t)b*NN + sel_idx[1][j])*HMM + h)*HDD + d;
                g_mem[mi] = g_mem[mi]*(1.0f - w*ee) + w*gv;
            }
        }
        __syncthreads();

        if (tid==0){
            volatile u32* p = &g_bar[b];
            while (*p < 1u*HMM*(unsigned)(t+1)) { }
        }
        __syncthreads();
    }
}

extern "C" void kernel_launch(void* const* d_in, const int* in_sizes, int n_in,
                              void* d_out, int out_size)
{
    const int*   ids      = (const int*)  d_in[0];
    const float* emb      = (const float*)d_in[1];
    const float* pos      = (const float*)d_in[2];
    const float* ln1_g    = (const float*)d_in[3];
    const float* ln1_b    = (const float*)d_in[4];
    const float* ln2_g    = (const float*)d_in[5];
    const float* ln2_b    = (const float*)d_in[6];
    const float* Wq       = (const float*)d_in[7];
    const float* Wk       = (const float*)d_in[8];
    const float* Wv       = (const float*)d_in[9];
    const float* Wo       = (const float*)d_in[10];
    const float* W1       = (const float*)d_in[11];
    const float* b1       = (const float*)d_in[12];
    const float* W2       = (const float*)d_in[13];
    const float* b2       = (const float*)d_in[14];
    const float* lnf_g    = (const float*)d_in[15];
    const float* lnf_b    = (const float*)d_in[16];
    const float* W_if_h   = (const float*)d_in[17];
    const float* W_if_r   = (const float*)d_in[18];
    const float* b_if     = (const float*)d_in[19];
    const float* W_lg_h   = (const float*)d_in[20];
    const float* W_lg_r   = (const float*)d_in[21];
    const float* b_lg     = (const float*)d_in[22];
    const float* beta_read  = (const float*)d_in[23];
    const float* beta_write = (const float*)d_in[24];
    const float* mem_init = (const float*)d_in[25];
    float* out = (float*)d_out;

    float *px,*phh,*pq,*pk,*pv,*po,*pu,*pif,*pcat;
    u32 *pwh,*pwl,*pah,*pal;
    cudaGetSymbolAddress((void**)&px,  g_x);
    cudaGetSymbolAddress((void**)&phh, g_h);
    cudaGetSymbolAddress((void**)&pq,  g_q);
    cudaGetSymbolAddress((void**)&pk,  g_k);
    cudaGetSymbolAddress((void**)&pv,  g_v);
    cudaGetSymbolAddress((void**)&po,  g_o);
    cudaGetSymbolAddress((void**)&pu,  g_u);
    cudaGetSymbolAddress((void**)&pif, g_iface);
    cudaGetSymbolAddress((void**)&pcat,g_cat);
    cudaGetSymbolAddress((void**)&pwh, g_wh);
    cudaGetSymbolAddress((void**)&pwl, g_wl);
    cudaGetSymbolAddress((void**)&pah, g_ah);
    cudaGetSymbolAddress((void**)&pal, g_al);

    const int M = BB*TT;

    // weight splits
    const float* qkvo[4] = {Wq, Wk, Wv, Wo};
    for (int l=0;l<LL;l++){
        for (int w=0;w<4;w++)
            wsplit_kernel<<<dim3(2,256),256>>>(qkvo[w] + (size_t)l*EE*EE,
                pwh + OFF_QKVO(l,w), pwl + OFF_QKVO(l,w), EE);
        wsplit_kernel<<<dim3(8,256),256>>>(W1 + (size_t)l*EE*FF, pwh + OFF_W1(l), pwl + OFF_W1(l), FF);
        wsplit_kernel<<<dim3(2,1024),256>>>(W2 + (size_t)l*FF*EE, pwh + OFF_W2(l), pwl + OFF_W2(l), EE);
    }
    wsplit_kernel<<<dim3(5,256),256>>>(W_if_h, pwh + OFF_WIFH, pwl + OFF_WIFH, IFF);
    wsplit_kernel<<<dim3(125,256),256>>>(W_lg_h, pwh + OFF_WLG, pwl + OFF_WLG, VV);
    wsplit_kernel<<<dim3(125,128),256>>>(W_lg_r, pwh + OFF_WLG + (size_t)256*VV,
                                         pwl + OFF_WLG + (size_t)256*VV, VV);

    embed_kernel<<<M,256>>>(ids, emb, pos);

    for (int l=0; l<LL; ++l){
        ln_kernel<<<M,256>>>(px, ln1_g + l*EE, ln1_b + l*EE, phh, EE);
        asplit_kernel<<<M,256>>>(phh, EE, pah, pal, 256, 0, 256);
        bgemm_kernel<false,false,false,false><<<dim3(4,16),256>>>(pah, pal, 256,
            pwh+OFF_QKVO(l,0), pwl+OFF_QKVO(l,0), nullptr, pq, EE, 256);
        bgemm_kernel<false,false,false,false><<<dim3(4,16),256>>>(pah, pal, 256,
            pwh+OFF_QKVO(l,1), pwl+OFF_QKVO(l,1), nullptr, pk, EE, 256);
        bgemm_kernel<false,false,false,false><<<dim3(4,16),256>>>(pah, pal, 256,
            pwh+OFF_QKVO(l,2), pwl+OFF_QKVO(l,2), nullptr, pv, EE, 256);
        attn_s_kernel<<<dim3(64, BB*HAA),256>>>();
        softmax_kernel<<<BB*HAA*TT,256>>>();
        attn_o_kernel<<<dim3(8, BB*HAA),256>>>();
        asplit_kernel<<<M,256>>>(po, EE, pah, pal, 256, 0, 256);
        bgemm_kernel<true,false,false,false><<<dim3(4,16),256>>>(pah, pal, 256,
            pwh+OFF_QKVO(l,3), pwl+OFF_QKVO(l,3), nullptr, px, EE, 256);
        ln_kernel<<<M,256>>>(px, ln2_g + l*EE, ln2_b + l*EE, phh, EE);
        asplit_kernel<<<M,256>>>(phh, EE, pah, pal, 256, 0, 256);
        bgemm_kernel<false,true,true,false><<<dim3(16,16),256>>>(pah, pal, 256,
            pwh+OFF_W1(l), pwl+OFF_W1(l), b1 + l*FF, pu, FF, 256);
        asplit_kernel<<<M,256>>>(pu, FF, pah, pal, 1024, 0, 1024);
        bgemm_kernel<true,false,true,false><<<dim3(4,16),256>>>(pah, pal, 1024,
            pwh+OFF_W2(l), pwl+OFF_W2(l), b2 + l*EE, px, EE, 1024);
    }

    // final LN -> g_cat cols [0,512); split h-part into planes (lda2=384)
    ln_kernel<<<M,256>>>(px, lnf_g, lnf_b, pcat, KCAT);
    asplit_kernel<<<M,256>>>(pcat, KCAT, pah, pal, 384, 0, 256);

    // iface = h @ W_if_h + b_if
    bgemm_kernel<false,false,true,true><<<dim3(9,16),256>>>(pah, pal, 384,
        pwh+OFF_WIFH, pwl+OFF_WIFH, b_if, pif, IFF, 256);

    meminit_kernel<<<16384,256>>>(mem_init);
    scaninit_kernel<<<8,256>>>();

    scan_persist_kernel<<<BB*HMM,256>>>(W_if_r, beta_read, beta_write);

    // split rv-carry part (cols 512..767) into planes kp 256..383
    asplit_kernel<<<M,256>>>(pcat + 512, KCAT, pah, pal, 384, 256, 128);

    // out = [h | rv] @ [W_lg_h ; W_lg_r] + b_lg
    bgemm_kernel<false,false,true,false><<<dim3(250,16),256>>>(pah, pal, 384,
        pwh+OFF_WLG, pwl+OFF_WLG, b_lg, out, VV, 384);
}

// round 9
// speedup vs baseline: 1.6641x; 1.1440x over previous
#include <cuda_runtime.h>
#include <math.h>

typedef unsigned int u32;

#define BB 8
#define TT 256
#define EE 512
#define FF 2048
#define DD 256
#define NN 2048
#define LL 2
#define VV 32000
#define HMM 4
#define HDD 64
#define HAA 8
#define DHH 64
#define IFF 1028
#define TOPKK 8
#define MAXSEL 64

// weight-plane arena offsets (u32 units). Per-weight contiguous across layers.
#define OFF_QKVO_W(w) ((w)*262144)             // + l*131072
#define OFF_W1  1048576                        // + l*524288
#define OFF_W2  2097152                        // + l*524288
#define OFF_WIFH 3145728
#define OFF_WLG  3408896
#define ARENA    15696896

// ---- scratch ----
__device__ float g_x[BB*TT*EE];
__device__ float g_q[BB*TT*EE];
__device__ float g_k[BB*TT*EE];
__device__ float g_v[BB*TT*EE];
__device__ float g_s[BB*HAA*TT*TT];
__device__ float g_iface[BB*TT*IFF];
__device__ float g_mem[BB*NN*HMM*HDD];
__device__ float g_norminv[BB*NN*HMM];
__device__ float g_rvbuf[2][BB*DD];
__device__ u32   g_bar[BB];
__device__ u32   g_wh[ARENA];
__device__ u32   g_wl[ARENA];
__device__ u32   g_ah[2048*1024];   // u planes (lda2=1024) / vocab-A planes (lda2=384)
__device__ u32   g_al[2048*1024];
__device__ u32   g_bh[2048*256];    // ln / attn_o planes (lda2=256)
__device__ u32   g_bl[2048*256];

__device__ __forceinline__ float gelu_f(float x){
    float x3 = x*x*x;
    return 0.5f*x*(1.0f+tanhf(0.7978845608028654f*(x+0.044715f*x3)));
}
__device__ __forceinline__ float sigmoid_f(float x){ return 1.0f/(1.0f+expf(-x)); }
__device__ __forceinline__ float softplus_clip(float x){
    float sp = fmaxf(x,0.0f) + log1pf(expf(-fabsf(x)));
    return fminf(fmaxf(sp,1.0f),20.0f);
}

__device__ __forceinline__ void packpair(float e, float o, u32 &hi, u32 &lo){
    u32 h; asm("cvt.rn.bf16x2.f32 %0, %1, %2;" : "=r"(h) : "f"(o), "f"(e));
    float he = __uint_as_float(h<<16);
    float ho = __uint_as_float(h & 0xffff0000u);
    asm("cvt.rn.bf16x2.f32 %0, %1, %2;" : "=r"(lo) : "f"(o-ho), "f"(e-he));
    hi = h;
}

__device__ __forceinline__ void mma_bf16(float* c, const u32* a, const u32* b){
    asm volatile("mma.sync.aligned.m16n8k16.row.col.f32.bf16.bf16.f32 "
        "{%0,%1,%2,%3}, {%4,%5,%6,%7}, {%8,%9}, {%0,%1,%2,%3};\n"
        : "+f"(c[0]), "+f"(c[1]), "+f"(c[2]), "+f"(c[3])
        : "r"(a[0]), "r"(a[1]), "r"(a[2]), "r"(a[3]), "r"(b[0]), "r"(b[1]));
}

__device__ __forceinline__ u32 s2u(const void* p){ return (u32)__cvta_generic_to_shared(p); }
__device__ __forceinline__ void cp16(u32 d, const void* s){
    asm volatile("cp.async.cg.shared.global [%0], [%1], 16;\n"::"r"(d),"l"(s));
}
__device__ __forceinline__ void cp16z(u32 d, const void* s, int sz){
    asm volatile("cp.async.cg.shared.global [%0], [%1], 16, %2;\n"::"r"(d),"l"(s),"r"(sz));
}
__device__ __forceinline__ void cp_commit(){ asm volatile("cp.async.commit_group;\n"); }
__device__ __forceinline__ void cp_wait0(){ asm volatile("cp.async.wait_group 0;\n"); }

__device__ __forceinline__ void red_release(u32* p, u32 v){
    asm volatile("red.release.gpu.global.add.u32 [%0], %1;" :: "l"(p), "r"(v) : "memory");
}
__device__ __forceinline__ u32 ld_acquire(const u32* p){
    u32 v; asm volatile("ld.acquire.gpu.global.u32 %0, [%1];" : "=r"(v) : "l"(p) : "memory");
    return v;
}

// ---- weight split: f32 [K][N] -> hi/lo u32 planes [K/2][N] ----
__global__ void wsplit_kernel(const float* __restrict__ src, u32* __restrict__ dh,
                              u32* __restrict__ dl, int N){
    int k2 = blockIdx.y;
    int n = blockIdx.x*256 + threadIdx.x;
    if (n >= N) return;
    float e = src[(size_t)(2*k2)*N + n];
    float o = src[(size_t)(2*k2+1)*N + n];
    u32 hi, lo; packpair(e, o, hi, lo);
    dh[(size_t)k2*N + n] = hi;
    dl[(size_t)k2*N + n] = lo;
}

// ---- embedding ----
__global__ void embed_kernel(const int* __restrict__ ids,
                             const float* __restrict__ emb,
                             const float* __restrict__ pos){
    int bt = blockIdx.x;
    int t = bt & (TT-1);
    int id = ids[bt];
    for (int e = threadIdx.x; e < EE; e += 256)
        g_x[(size_t)bt*EE + e] = emb[(size_t)id*EE + e] + pos[(size_t)t*EE + e];
}

// ---- layernorm with split (plane) output ----
__global__ void ln_split_kernel(const float* __restrict__ x, const float* __restrict__ g,
                                const float* __restrict__ bb, u32* __restrict__ oh,
                                u32* __restrict__ ol, int lda2){
    int row = blockIdx.x, tid = threadIdx.x;
    __shared__ float red[256];
    const float* xr = x + (size_t)row*EE;
    float v0 = xr[2*tid], v1 = xr[2*tid+1];
    red[tid] = v0+v1; __syncthreads();
    for (int s=128;s>0;s>>=1){ if (tid<s) red[tid]+=red[tid+s]; __syncthreads(); }
    float m = red[0] * (1.0f/EE);
    __syncthreads();
    float d0=v0-m, d1=v1-m;
    red[tid] = d0*d0 + d1*d1; __syncthreads();
    for (int s=128;s>0;s>>=1){ if (tid<s) red[tid]+=red[tid+s]; __syncthreads(); }
    float rs = rsqrtf(red[0]*(1.0f/EE) + 1e-5f);
    float y0 = d0*rs*g[2*tid]   + bb[2*tid];
    float y1 = d1*rs*g[2*tid+1] + bb[2*tid+1];
    u32 hi, lo; packpair(y0, y1, hi, lo);
    oh[(size_t)row*lda2 + tid] = hi;
    ol[(size_t)row*lda2 + tid] = lo;
}

// ---- bf16x3 tensor GEMM, cp.async double-buffered; optional split-plane output ----
template<bool ACC, bool GELU, bool BIAS, bool NGUARD, bool OSPLIT>
__global__ __launch_bounds__(256)
void bgemm_kernel(const u32* __restrict__ AH, const u32* __restrict__ AL, int lda2,
                  const u32* __restrict__ BH, const u32* __restrict__ BL,
                  const float* __restrict__ bias, float* __restrict__ C,
                  u32* __restrict__ OH, u32* __restrict__ OL, int lda2o,
                  int N, int K2)
{
    __shared__ u32 AsH[2][128*12], AsL[2][128*12];
    __shared__ u32 BsH[2][8][136], BsL[2][8][136];
    int tid = threadIdx.x;
    int bm = blockIdx.y*128, bn = blockIdx.x*128;
    int warp = tid>>5, lane = tid&31;
    int wm = (warp>>2)*64, wn = (warp&3)*32;
    int gid = lane>>2, tig = lane&3;

    float c[4][4][4];
    #pragma unroll
    for (int mt=0;mt<4;mt++)
        #pragma unroll
        for (int nt=0;nt<4;nt++)
            #pragma unroll
            for (int i=0;i<4;i++) c[mt][nt][i]=0.f;

    int am = tid & 127, akp = (tid>>7)*4;
    int bk = tid>>5, bn4 = lane*4;
    const u32* AHp = AH + (size_t)(bm+am)*lda2 + akp;
    const u32* ALp = AL + (size_t)(bm+am)*lda2 + akp;
    int nit = K2/8;

    auto issueTile = [&](int buf, int it){
        cp16(s2u(&AsH[buf][am*12+akp]), AHp + (size_t)it*8);
        cp16(s2u(&AsL[buf][am*12+akp]), ALp + (size_t)it*8);
        int kr = it*8 + bk;
        const u32* ph_ = BH + (size_t)kr*N + bn + bn4;
        const u32* pl_ = BL + (size_t)kr*N + bn + bn4;
        if (!NGUARD){
            cp16(s2u(&BsH[buf][bk][bn4]), ph_);
            cp16(s2u(&BsL[buf][bk][bn4]), pl_);
        } else {
            int col = bn + bn4;
            int sz = (N - col)*4; sz = sz<0?0:(sz>16?16:sz);
            cp16z(s2u(&BsH[buf][bk][bn4]), ph_, sz);
            cp16z(s2u(&BsL[buf][bk][bn4]), pl_, sz);
        }
    };

    issueTile(0, 0); cp_commit();

    int cur = 0;
    for (int it=0; it<nit; ++it){
        cp_wait0();
        __syncthreads();
        if (it+1 < nit){ issueTile(cur^1, it+1); cp_commit(); }

        u32 aH[4][4], aL[4][4];
        #pragma unroll
        for (int mt=0;mt<4;mt++){
            int m0 = wm + mt*16 + gid;
            aH[mt][0]=AsH[cur][m0*12     + tig  ]; aL[mt][0]=AsL[cur][m0*12     + tig  ];
            aH[mt][1]=AsH[cur][(m0+8)*12 + tig  ]; aL[mt][1]=AsL[cur][(m0+8)*12 + tig  ];
            aH[mt][2]=AsH[cur][m0*12     + tig+4]; aL[mt][2]=AsL[cur][m0*12     + tig+4];
            aH[mt][3]=AsH[cur][(m0+8)*12 + tig+4]; aL[mt][3]=AsL[cur][(m0+8)*12 + tig+4];
        }
        u32 bH[4][2], bL[4][2];
        #pragma unroll
        for (int nt=0;nt<4;nt++){
            int n0 = wn + nt*8 + gid;
            bH[nt][0]=BsH[cur][tig  ][n0]; bL[nt][0]=BsL[cur][tig  ][n0];
            bH[nt][1]=BsH[cur][tig+4][n0]; bL[nt][1]=BsL[cur][tig+4][n0];
        }
        #pragma unroll
        for (int mt=0;mt<4;mt++){
            #pragma unroll
            for (int nt=0;nt<4;nt++){
                mma_bf16(c[mt][nt], aH[mt], bH[nt]);
                mma_bf16(c[mt][nt], aH[mt], bL[nt]);
                mma_bf16(c[mt][nt], aL[mt], bH[nt]);
            }
        }
        cur ^= 1;
    }

    #pragma unroll
    for (int mt=0;mt<4;mt++){
        int ra = bm + wm + mt*16 + gid;
        int rb = ra + 8;
        #pragma unroll
        for (int nt=0;nt<4;nt++){
            int col = bn + wn + nt*8 + tig*2;
            if (OSPLIT){
                float v0 = c[mt][nt][0], v1 = c[mt][nt][1];
                float v2 = c[mt][nt][2], v3 = c[mt][nt][3];
                if (BIAS){ float b0=bias[col], b1=bias[col+1]; v0+=b0; v1+=b1; v2+=b0; v3+=b1; }
                if (GELU){ v0=gelu_f(v0); v1=gelu_f(v1); v2=gelu_f(v2); v3=gelu_f(v3); }
                u32 hi, lo;
                packpair(v0, v1, hi, lo);
                OH[(size_t)ra*lda2o + (col>>1)] = hi; OL[(size_t)ra*lda2o + (col>>1)] = lo;
                packpair(v2, v3, hi, lo);
                OH[(size_t)rb*lda2o + (col>>1)] = hi; OL[(size_t)rb*lda2o + (col>>1)] = lo;
            } else {
                #pragma unroll
                for (int q=0;q<4;q++){
                    int r = (q<2)? ra : rb;
                    int cc = col + (q&1);
                    if (NGUARD && cc >= N) continue;
                    float v = c[mt][nt][q];
                    if (BIAS) v += bias[cc];
                    if (GELU) v = gelu_f(v);
                    size_t idx = (size_t)r*N + cc;
                    if (ACC) v += C[idx];
                    C[idx] = v;
                }
            }
        }
    }
}

// ---- attention ----
__global__ void attn_s_kernel(){
    int bh = blockIdx.y;
    int b = bh >> 3, h = bh & 7;
    int qt = blockIdx.x >> 3, kt = blockIdx.x & 7;
    __shared__ float Qs[32][65];
    __shared__ float Ks[32][65];
    int tid = threadIdx.x;
    {
        int r = tid >> 3, cc = (tid & 7)*8;
        const float* qsrc = g_q + ((size_t)(b*TT + qt*32 + r))*EE + h*DHH + cc;
        const float* ksrc = g_k + ((size_t)(b*TT + kt*32 + r))*EE + h*DHH + cc;
        float4 q0 = *(const float4*)qsrc, q1 = *(const float4*)(qsrc+4);
        float4 k0 = *(const float4*)ksrc, k1 = *(const float4*)(ksrc+4);
        Qs[r][cc+0]=q0.x; Qs[r][cc+1]=q0.y; Qs[r][cc+2]=q0.z; Qs[r][cc+3]=q0.w;
        Qs[r][cc+4]=q1.x; Qs[r][cc+5]=q1.y; Qs[r][cc+6]=q1.z; Qs[r][cc+7]=q1.w;
        Ks[r][cc+0]=k0.x; Ks[r][cc+1]=k0.y; Ks[r][cc+2]=k0.z; Ks[r][cc+3]=k0.w;
        Ks[r][cc+4]=k1.x; Ks[r][cc+5]=k1.y; Ks[r][cc+6]=k1.z; Ks[r][cc+7]=k1.w;
    }
    __syncthreads();
    int r = tid & 31, gq = tid >> 5;
    float a0=0,a1=0,a2=0,a3=0;
    #pragma unroll
    for (int kk=0;kk<64;kk++){
        float qv = Qs[r][kk];
        a0 += qv*Ks[gq*4+0][kk];
        a1 += qv*Ks[gq*4+1][kk];
        a2 += qv*Ks[gq*4+2][kk];
        a3 += qv*Ks[gq*4+3][kk];
    }
    int qrow = qt*32 + r;
    int kc = kt*32 + gq*4;
    float* srow = g_s + ((size_t)bh*TT + qrow)*TT + kc;
    srow[0] = (kc+0<=qrow)? a0*0.125f : -1e30f;
    srow[1] = (kc+1<=qrow)? a1*0.125f : -1e30f;
    srow[2] = (kc+2<=qrow)? a2*0.125f : -1e30f;
    srow[3] = (kc+3<=qrow)? a3*0.125f : -1e30f;
}

__global__ void softmax_kernel(){
    int row = blockIdx.x, tid = threadIdx.x;
    __shared__ float red[256];
    float* sp = g_s + (size_t)row*TT;
    float v = sp[tid];
    red[tid]=v; __syncthreads();
    for (int s=128;s>0;s>>=1){ if (tid<s) red[tid]=fmaxf(red[tid],red[tid+s]); __syncthreads(); }
    float m = red[0]; __syncthreads();
    float e = expf(v-m);
    red[tid]=e; __syncthreads();
    for (int s=128;s>0;s>>=1){ if (tid<s) red[tid]+=red[tid+s]; __syncthreads(); }
    sp[tid] = e / red[0];
}

// O = A @ V, packed directly into bf16 hi/lo planes (g_bh/g_bl, lda2=256)
__global__ void attn_o_kernel(){
    int bh = blockIdx.y;
    int b = bh >> 3, h = bh & 7;
    int qt = blockIdx.x;
    __shared__ float As[32][65];
    __shared__ float Vs[64][64];
    int tid = threadIdx.x;
    int d = tid & 63, qg = tid >> 6;
    float acc[8];
    #pragma unroll
    for (int i=0;i<8;i++) acc[i]=0.f;
    for (int k0=0;k0<TT;k0+=64){
        {
            int r = tid >> 3, cc = (tid & 7)*8;
            const float* src = g_s + ((size_t)bh*TT + qt*32 + r)*TT + k0 + cc;
            float4 a0=*(const float4*)src, a1=*(const float4*)(src+4);
            As[r][cc+0]=a0.x; As[r][cc+1]=a0.y; As[r][cc+2]=a0.z; As[r][cc+3]=a0.w;
            As[r][cc+4]=a1.x; As[r][cc+5]=a1.y; As[r][cc+6]=a1.z; As[r][cc+7]=a1.w;
        }
        #pragma unroll
        for (int i=0;i<4;i++){
            int fl = (tid + 256*i)*4;
            int r = fl >> 6, cc = fl & 63;
            float4 vv = *(const float4*)(g_v + ((size_t)(b*TT + k0 + r))*EE + h*DHH + cc);
            *(float4*)&Vs[r][cc] = vv;
        }
        __syncthreads();
        #pragma unroll
        for (int kk=0;kk<64;kk++){
            float vv = Vs[kk][d];
            #pragma unroll
            for (int i=0;i<8;i++) acc[i] += As[qg*8+i][kk]*vv;
        }
        __syncthreads();
    }
    #pragma unroll
    for (int i=0;i<8;i++){
        int qr = qt*32 + qg*8 + i;
        float other = __shfl_xor_sync(0xffffffffu, acc[i], 1);
        if ((d & 1) == 0){
            u32 hi, lo; packpair(acc[i], other, hi, lo);
            int pc = (h*DHH + d) >> 1;
            size_t row = (size_t)(b*TT + qr);
            g_bh[row*256 + pc] = hi;
            g_bl[row*256 + pc] = lo;
        }
    }
}

// ---- init ----
__global__ void meminit_kernel(const float* __restrict__ mi){
    int idx = blockIdx.x*256 + threadIdx.x;
    g_mem[idx] = mi[idx & (NN*DD - 1)];
}
__global__ void norminit_kernel(){
    int gw = blockIdx.x*8 + (threadIdx.x>>5);
    int lane = threadIdx.x & 31;
    const float2* mrow = (const float2*)(g_mem + (size_t)gw*HDD);
    float2 v = mrow[lane];
    float ss = v.x*v.x + v.y*v.y;
    #pragma unroll
    for (int o=16;o>0;o>>=1) ss += __shfl_xor_sync(0xffffffffu, ss, o);
    if (lane==0) g_norminv[gw] = rsqrtf(ss + 1e-8f);
}
__global__ void scaninit_kernel(){
    int i = blockIdx.x*256 + threadIdx.x;
    g_rvbuf[0][i] = 0.f;
    if (i < BB) g_bar[i] = 0u;
}

// ---- persistent fused scan ----
__global__ __launch_bounds__(256,1)
void scan_persist_kernel(const float* __restrict__ Wr,
                         const float* __restrict__ pbr,
                         const float* __restrict__ pbw)
{
    int bh = blockIdx.x;
    int b = bh >> 2, h = bh & 3;
    int tid = threadIdx.x, warp = tid>>5, lane = tid&31;

    __shared__ float rv_s[DD];
    __shared__ float ifc_s[256];
    __shared__ float pmat[4][256];
    __shared__ __align__(16) float knr[HDD];
    __shared__ __align__(16) float knw[HDD];
    __shared__ float simr[NN], simw[NN];
    __shared__ float gr_sh;
    __shared__ float candv[2][32];
    __shared__ float s_kth[2], s_smax[2];
    __shared__ int   s_cnt[2];
    __shared__ int   sel_idx[2][MAXSEL];
    __shared__ float sel_w[2][MAXSEL];
    __shared__ float s_inv[2];

    float beta_r = softplus_clip(*pbr);
    float beta_w = softplus_clip(*pbw);

    for (int t=0; t<TT; ++t){
        rv_s[tid] = __ldcg(&g_rvbuf[t&1][b*DD + tid]);
        if (tid==0){ s_cnt[0]=0; s_cnt[1]=0; }
        __syncthreads();
        // record rv carry directly as bf16 split planes (cols 256..383 of vocab A)
        if (h == 0 && tid < 128){
            u32 hi, lo; packpair(rv_s[2*tid], rv_s[2*tid+1], hi, lo);
            size_t row = (size_t)(b*TT + t);
            g_ah[row*384 + 256 + tid] = hi;
            g_al[row*384 + 256 + tid] = lo;
        }

        // iface matvec: float4 loads, 4-way d-split (Wr slice L1-resident: no fences flush L1)
        {
            int cq = tid & 63, dg = tid >> 6;
            int seg = cq >> 4, cl4 = (cq & 15)*4;
            int col = seg*DD + h*HDD + cl4;
            const float* wp = Wr + (size_t)(dg*64)*IFF + col;
            float ax=0.f, ay=0.f, az=0.f, aw=0.f;
            #pragma unroll 8
            for (int d=0; d<64; ++d){
                float r = rv_s[dg*64 + d];
                float4 w = *reinterpret_cast<const float4*>(wp + (size_t)d*IFF);
                ax += r*w.x; ay += r*w.y; az += r*w.z; aw += r*w.w;
            }
            int p = seg*64 + cl4;
            pmat[dg][p+0]=ax; pmat[dg][p+1]=ay; pmat[dg][p+2]=az; pmat[dg][p+3]=aw;
        }
        if (tid < 32){
            int col = 4*DD + h;
            float acc = 0.f;
            for (int d=tid; d<DD; d+=32) acc += rv_s[d]*Wr[(size_t)d*IFF + col];
            #pragma unroll
            for (int o=16;o>0;o>>=1) acc += __shfl_xor_sync(0xffffffffu, acc, o);
            if (tid==0) gr_sh = acc + g_iface[(size_t)(b*TT + t)*IFF + col];
        }
        __syncthreads();
        {
            int grp = tid >> 6, l = tid & 63;
            int col = grp*DD + h*HDD + l;
            ifc_s[tid] = g_iface[(size_t)(b*TT + t)*IFF + col]
                       + pmat[0][tid] + pmat[1][tid] + pmat[2][tid] + pmat[3][tid];
        }
        __syncthreads();

        // normalize keys
        if (tid < 64){
            int w = tid >> 5, l = tid & 31;
            float v0 = ifc_s[w*64 + l], v1 = ifc_s[w*64 + l + 32];
            float ss = v0*v0 + v1*v1;
            #pragma unroll
            for (int o=16;o>0;o>>=1) ss += __shfl_xor_sync(0xffffffffu, ss, o);
            float rn = rsqrtf(ss + 1e-8f);
            float* dst = w ? knw : knr;
            dst[l] = v0*rn; dst[l+32] = v1*rn;
        }
        __syncthreads();

        // sims: one thread per row, cached inverse norms, zero shuffles
        for (int j=0;j<8;j++){
            int n = j*256 + tid;
            const float4* mrow = (const float4*)(g_mem + (((size_t)b*NN + n)*HMM + h)*HDD);
            float dr=0.f, dw=0.f;
            #pragma unroll
            for (int c2=0;c2<16;c2++){
                float4 m  = mrow[c2];
                float4 kr = *(const float4*)&knr[c2*4];
                float4 kw = *(const float4*)&knw[c2*4];
                dr += m.x*kr.x + m.y*kr.y + m.z*kr.z + m.w*kr.w;
                dw += m.x*kw.x + m.y*kw.y + m.z*kw.z + m.w*kw.w;
            }
            float ninv = g_norminv[((size_t)b*NN + n)*HMM + h];
            simr[n] = dr*ninv;
            simw[n] = dw*ninv;
        }
        __syncthreads();

        // warp-parallel topk: warps 0-3 read-phase, warps 4-7 write-phase
        {
            int ph = warp >> 2, wi = warp & 3;
            const float* sim = ph ? simw : simr;
            float lv[16];
            #pragma unroll
            for (int j=0;j<16;j++) lv[j] = sim[wi*512 + j*32 + lane];
            #pragma unroll
            for (int it=0; it<TOPKK; ++it){
                float m=-3.4e38f; int mi=0;
                #pragma unroll
                for (int j=0;j<16;j++) if (lv[j]>m){ m=lv[j]; mi=j; }
                float bm=m; int bl=lane;
                #pragma unroll
                for (int o=16;o>0;o>>=1){
                    float om=__shfl_xor_sync(0xffffffffu,bm,o);
                    int   ol=__shfl_xor_sync(0xffffffffu,bl,o);
                    if (om>bm || (om==bm && ol<bl)){ bm=om; bl=ol; }
                }
                if (lane==bl) lv[mi] = -3.4e38f;
                if (lane==0) candv[ph][wi*8+it] = bm;
            }
        }
        __syncthreads();
        if ((warp&3)==0){
            int ph = warp>>2;
            float v = candv[ph][lane];
            float kth_=0.f, smax_=0.f;
            #pragma unroll
            for (int it=0; it<TOPKK; ++it){
                float bm=v; int bl=lane;
                #pragma unroll
                for (int o=16;o>0;o>>=1){
                    float om=__shfl_xor_sync(0xffffffffu,bm,o);
                    int   ol=__shfl_xor_sync(0xffffffffu,bl,o);
                    if (om>bm || (om==bm && ol<bl)){ bm=om; bl=ol; }
                }
                if (it==0) smax_=bm;
                if (it==TOPKK-1) kth_=bm;
                if (lane==bl) v = -3.4e38f;
            }
            if (lane==0){ s_kth[ph]=kth_; s_smax[ph]=smax_; }
        }
        __syncthreads();

        // selection split 128/128 over phases
        {
            int ph = tid >> 7, lt = tid & 127;
            const float* sim = ph ? simw : simr;
            float kth = s_kth[ph], smax = s_smax[ph];
            float beta = ph ? beta_w : beta_r;
            #pragma unroll
            for (int j=0;j<16;j++){
                int i = j*128 + lt;
                float v = sim[i];
                if (v >= kth){
                    int p = atomicAdd(&s_cnt[ph], 1);
                    if (p < MAXSEL){ sel_idx[ph][p]=i; sel_w[ph][p]=expf(beta*(v-smax)); }
                }
            }
        }
        __syncthreads();
        if (tid < 2){
            int cnt = min(s_cnt[tid], MAXSEL);
            float ds=0.f;
            for (int j=0;j<cnt;j++) ds += sel_w[tid][j];
            s_inv[tid] = 1.0f/ds;
        }
        __syncthreads();

        // read gather (before write updates memory)
        {
            int cnt = min(s_cnt[0], MAXSEL);
            if (tid < HDD){
                float acc=0.f;
                float invd = s_inv[0];
                for (int j=0;j<cnt;j++)
                    acc += sel_w[0][j]*invd * g_mem[(((size_t)b*NN + sel_idx[0][j])*HMM + h)*HDD + tid];
                __stcg(&g_rvbuf[(t+1)&1][b*DD + h*HDD + tid], acc);
            }
        }
        __syncthreads();
        if (tid==0) red_release(&g_bar[b], 1u);   // release: orders stcg rv stores; no L1 flush

        // write update (block-private rows)
        {
            int cnt = min(s_cnt[1], MAXSEL);
            float gg = sigmoid_f(gr_sh);
            int d = tid & 63;
            float ee = sigmoid_f(ifc_s[192 + d]);
            float gv = gg * ifc_s[128 + d];
            float invd = s_inv[1];
            for (int j = tid>>6; j<cnt; j+=4){
                float w = sel_w[1][j]*invd;
                size_t mi = (((size_t)b*NN + sel_idx[1][j])*HMM + h)*HDD + d;
                g_mem[mi] = g_mem[mi]*(1.0f - w*ee) + w*gv;
            }
        }
        __syncthreads();
        // refresh cached inverse norms for updated rows (one warp per row)
        {
            int cnt = min(s_cnt[1], MAXSEL);
            for (int j = warp; j < cnt; j += 8){
                int n = sel_idx[1][j];
                const float2* mrow = (const float2*)(g_mem + (((size_t)b*NN + n)*HMM + h)*HDD);
                float2 v = mrow[lane];
                float ss = v.x*v.x + v.y*v.y;
                #pragma unroll
                for (int o=16;o>0;o>>=1) ss += __shfl_xor_sync(0xffffffffu, ss, o);
                if (lane==0) g_norminv[((size_t)b*NN + n)*HMM + h] = rsqrtf(ss + 1e-8f);
            }
        }
        __syncthreads();

        if (tid==0){
            while (ld_acquire(&g_bar[b]) < (u32)HMM*(u32)(t+1)) { }
        }
        __syncthreads();
    }
}

extern "C" void kernel_launch(void* const* d_in, const int* in_sizes, int n_in,
                              void* d_out, int out_size)
{
    const int*   ids      = (const int*)  d_in[0];
    const float* emb      = (const float*)d_in[1];
    const float* pos      = (const float*)d_in[2];
    const float* ln1_g    = (const float*)d_in[3];
    const float* ln1_b    = (const float*)d_in[4];
    const float* ln2_g    = (const float*)d_in[5];
    const float* ln2_b    = (const float*)d_in[6];
    const float* Wq       = (const float*)d_in[7];
    const float* Wk       = (const float*)d_in[8];
    const float* Wv       = (const float*)d_in[9];
    const float* Wo       = (const float*)d_in[10];
    const float* W1       = (const float*)d_in[11];
    const float* b1       = (const float*)d_in[12];
    const float* W2       = (const float*)d_in[13];
    const float* b2       = (const float*)d_in[14];
    const float* lnf_g    = (const float*)d_in[15];
    const float* lnf_b    = (const float*)d_in[16];
    const float* W_if_h   = (const float*)d_in[17];
    const float* W_if_r   = (const float*)d_in[18];
    const float* b_if     = (const float*)d_in[19];
    const float* W_lg_h   = (const float*)d_in[20];
    const float* W_lg_r   = (const float*)d_in[21];
    const float* b_lg     = (const float*)d_in[22];
    const float* beta_read  = (const float*)d_in[23];
    const float* beta_write = (const float*)d_in[24];
    const float* mem_init = (const float*)d_in[25];
    float* out = (float*)d_out;

    float *px,*pq,*pk,*pv,*pif;
    u32 *pwh,*pwl,*pah,*pal,*pbh,*pbl;
    cudaGetSymbolAddress((void**)&px,  g_x);
    cudaGetSymbolAddress((void**)&pq,  g_q);
    cudaGetSymbolAddress((void**)&pk,  g_k);
    cudaGetSymbolAddress((void**)&pv,  g_v);
    cudaGetSymbolAddress((void**)&pif, g_iface);
    cudaGetSymbolAddress((void**)&pwh, g_wh);
    cudaGetSymbolAddress((void**)&pwl, g_wl);
    cudaGetSymbolAddress((void**)&pah, g_ah);
    cudaGetSymbolAddress((void**)&pal, g_al);
    cudaGetSymbolAddress((void**)&pbh, g_bh);
    cudaGetSymbolAddress((void**)&pbl, g_bl);

    const int M = BB*TT;

    // launches 1-5, so launch #6 (ncu -s 5 -c 1) is a bgemm
    embed_kernel<<<M,256>>>(ids, emb, pos);                                   // 1
    wsplit_kernel<<<dim3(2,512),256>>>(Wq, pwh+OFF_QKVO_W(0), pwl+OFF_QKVO_W(0), EE); // 2 (both layers)
    wsplit_kernel<<<dim3(2,512),256>>>(Wk, pwh+OFF_QKVO_W(1), pwl+OFF_QKVO_W(1), EE); // 3
    wsplit_kernel<<<dim3(2,512),256>>>(Wv, pwh+OFF_QKVO_W(2), pwl+OFF_QKVO_W(2), EE); // 4

    for (int l=0; l<LL; ++l){
        ln_split_kernel<<<M,256>>>(px, ln1_g + l*EE, ln1_b + l*EE, pbh, pbl, 256);    // 5
        bgemm_kernel<false,false,false,false,false><<<dim3(4,16),256>>>(pbh, pbl, 256,
            pwh+OFF_QKVO_W(0)+l*131072, pwl+OFF_QKVO_W(0)+l*131072,
            nullptr, pq, nullptr, nullptr, 0, EE, 256);                               // 6 <- profiled
        bgemm_kernel<false,false,false,false,false><<<dim3(4,16),256>>>(pbh, pbl, 256,
            pwh+OFF_QKVO_W(1)+l*131072, pwl+OFF_QKVO_W(1)+l*131072,
            nullptr, pk, nullptr, nullptr, 0, EE, 256);
        bgemm_kernel<false,false,false,false,false><<<dim3(4,16),256>>>(pbh, pbl, 256,
            pwh+OFF_QKVO_W(2)+l*131072, pwl+OFF_QKVO_W(2)+l*131072,
            nullptr, pv, nullptr, nullptr, 0, EE, 256);
        attn_s_kernel<<<dim3(64, BB*HAA),256>>>();
        softmax_kernel<<<BB*HAA*TT,256>>>();
        attn_o_kernel<<<dim3(8, BB*HAA),256>>>();   // writes planes into g_bh/g_bl
        if (l==0)
            wsplit_kernel<<<dim3(2,512),256>>>(Wo, pwh+OFF_QKVO_W(3), pwl+OFF_QKVO_W(3), EE);
        bgemm_kernel<true,false,false,false,false><<<dim3(4,16),256>>>(pbh, pbl, 256,
            pwh+OFF_QKVO_W(3)+l*131072, pwl+OFF_QKVO_W(3)+l*131072,
            nullptr, px, nullptr, nullptr, 0, EE, 256);
        ln_split_kernel<<<M,256>>>(px, ln2_g + l*EE, ln2_b + l*EE, pbh, pbl, 256);
        if (l==0){
            wsplit_kernel<<<dim3(8,512),256>>>(W1, pwh+OFF_W1, pwl+OFF_W1, FF);
            wsplit_kernel<<<dim3(2,2048),256>>>(W2, pwh+OFF_W2, pwl+OFF_W2, EE);
        }
        bgemm_kernel<false,true,true,false,true><<<dim3(16,16),256>>>(pbh, pbl, 256,
            pwh+OFF_W1+l*524288, pwl+OFF_W1+l*524288,
            b1 + l*FF, nullptr, pah, pal, 1024, FF, 256);   // gelu(h@W1+b1) -> u planes
        bgemm_kernel<true,false,true,false,false><<<dim3(4,16),256>>>(pah, pal, 1024,
            pwh+OFF_W2+l*524288, pwl+OFF_W2+l*524288,
            b2 + l*EE, px, nullptr, nullptr, 0, EE, 1024);
    }

    // final LN -> vocab-A planes cols [0,256)
    ln_split_kernel<<<M,256>>>(px, lnf_g, lnf_b, pah, pal, 384);

    // iface = h @ W_if_h + b_if
    wsplit_kernel<<<dim3(5,256),256>>>(W_if_h, pwh+OFF_WIFH, pwl+OFF_WIFH, IFF);
    bgemm_kernel<false,false,true,true,false><<<dim3(9,16),256>>>(pah, pal, 384,
        pwh+OFF_WIFH, pwl+OFF_WIFH, b_if, pif, nullptr, nullptr, 0, IFF, 256);

    // vocab weight splits (can overlap scan region in stream order; serial is fine)
    wsplit_kernel<<<dim3(125,256),256>>>(W_lg_h, pwh+OFF_WLG, pwl+OFF_WLG, VV);
    wsplit_kernel<<<dim3(125,128),256>>>(W_lg_r, pwh+OFF_WLG+(size_t)256*VV,
                                         pwl+OFF_WLG+(size_t)256*VV, VV);

    meminit_kernel<<<16384,256>>>(mem_init);
    norminit_kernel<<<BB*NN*HMM/8,256>>>();
    scaninit_kernel<<<8,256>>>();

    scan_persist_kernel<<<BB*HMM,256>>>(W_if_r, beta_read, beta_write);

    // out = [h | rv] @ [W_lg_h ; W_lg_r] + b_lg
    bgemm_kernel<false,false,true,false,false><<<dim3(250,16),256>>>(pah, pal, 384,
        pwh+OFF_WLG, pwl+OFF_WLG, b_lg, out, nullptr, nullptr, 0, VV, 384);
}